// round 5
// baseline (speedup 1.0000x reference)
#include <cuda_runtime.h>
#include <cuda_bf16.h>
#include <math.h>
#include <stdint.h>

#define BATCH   2
#define SEQ     2048
#define DMODEL  1024
#define NHEADS  16
#define HDIM    64
#define MROWS   (BATCH*SEQ)        // 4096
#define EDIM    (3*DMODEL)         // 3072
#define K3      (3*DMODEL)         // expanded split-K = 3072
#define NKT     (K3/64)            // 48 k-chunks of 64
#define BH      (BATCH*NHEADS)     // 32

// Scratch (device globals; no runtime allocation allowed)
__device__ __align__(128) __nv_bfloat16 g_abf[MROWS*K3];     // A' (hi,lo,hi)
__device__ __align__(128) __nv_bfloat16 g_bbf[EDIM*K3];      // B' for w_qkv
__device__ __align__(128) __nv_bfloat16 g_bbf2[DMODEL*K3];   // B' for w_out
__device__ float g_qkv[MROWS*EDIM];
// head-major split q/k/v: [section(q,k,v)][part(hi,lo)][bh][t][d]
__device__ __align__(128) __nv_bfloat16 g_split[(size_t)6*BH*SEQ*HDIM];
#define SEC_ELEMS ((size_t)BH*SEQ*HDIM)

// ===========================================================================
// helpers
// ===========================================================================
__device__ __forceinline__ uint32_t smem_u32(const void* p) {
    uint32_t a;
    asm("{ .reg .u64 t; cvta.to.shared.u64 t, %1; cvt.u32.u64 %0, t; }" : "=r"(a) : "l"(p));
    return a;
}
__device__ __forceinline__ void cp16(uint32_t smem, const void* g) {
    asm volatile("cp.async.cg.shared.global [%0], [%1], 16;" :: "r"(smem), "l"(g) : "memory");
}
__device__ __forceinline__ void cp_commit() {
    asm volatile("cp.async.commit_group;" ::: "memory");
}
template<int N> __device__ __forceinline__ void cp_wait() {
    asm volatile("cp.async.wait_group %0;" :: "n"(N) : "memory");
}
__device__ __forceinline__ void ldsm4(uint32_t& r0, uint32_t& r1, uint32_t& r2, uint32_t& r3,
                                      uint32_t addr) {
    asm volatile("ldmatrix.sync.aligned.m8n8.x4.shared.b16 {%0,%1,%2,%3}, [%4];"
                 : "=r"(r0), "=r"(r1), "=r"(r2), "=r"(r3) : "r"(addr));
}
__device__ __forceinline__ void ldsm4t(uint32_t& r0, uint32_t& r1, uint32_t& r2, uint32_t& r3,
                                       uint32_t addr) {
    asm volatile("ldmatrix.sync.aligned.m8n8.x4.trans.shared.b16 {%0,%1,%2,%3}, [%4];"
                 : "=r"(r0), "=r"(r1), "=r"(r2), "=r"(r3) : "r"(addr));
}
__device__ __forceinline__ void mma16816(float* d, const uint32_t* a, const uint32_t* b) {
    asm volatile("mma.sync.aligned.m16n8k16.row.col.f32.bf16.bf16.f32 "
                 "{%0,%1,%2,%3}, {%4,%5,%6,%7}, {%8,%9}, {%0,%1,%2,%3};"
                 : "+f"(d[0]), "+f"(d[1]), "+f"(d[2]), "+f"(d[3])
                 : "r"(a[0]), "r"(a[1]), "r"(a[2]), "r"(a[3]), "r"(b[0]), "r"(b[1]));
}
__device__ __forceinline__ uint32_t pack_bf16(float a, float b) {
    __nv_bfloat162 t = __floats2bfloat162_rn(a, b);
    return *(uint32_t*)&t;
}

// ===========================================================================
// K1: RMSNorm -> bf16-split A' (hi, lo, hi).
// ===========================================================================
__global__ void rmsnorm_kernel(const float* __restrict__ x, const float* __restrict__ w) {
    int row = blockIdx.x;
    int tid = threadIdx.x;
    const float* xr = x + (size_t)row * DMODEL;
    float v[4];
    float ss = 0.f;
#pragma unroll
    for (int i = 0; i < 4; i++) { v[i] = xr[tid + i*256]; ss += v[i]*v[i]; }
    __shared__ float red[256];
    red[tid] = ss;
    __syncthreads();
#pragma unroll
    for (int off = 128; off > 0; off >>= 1) {
        if (tid < off) red[tid] += red[tid + off];
        __syncthreads();
    }
    float inv = rsqrtf(red[0] * (1.0f / DMODEL) + 1e-6f);
    __nv_bfloat16* d = g_abf + (size_t)row * K3;
#pragma unroll
    for (int i = 0; i < 4; i++) {
        int col = tid + i*256;
        float y = v[i] * inv * w[col];
        __nv_bfloat16 hi = __float2bfloat16(y);
        __nv_bfloat16 lo = __float2bfloat16(y - __bfloat162float(hi));
        d[col] = hi; d[DMODEL + col] = lo; d[2*DMODEL + col] = hi;
    }
}

// ===========================================================================
// Weight conversion: fp32 [rows,1024] -> bf16-split [rows,3072] (hi,hi,lo)
// ===========================================================================
__global__ void convert_w_kernel(const float* __restrict__ src, __nv_bfloat16* __restrict__ dst,
                                 int total) {
    int idx = blockIdx.x * 256 + threadIdx.x;
    if (idx >= total) return;
    int n = idx >> 10, k = idx & 1023;
    float x = src[idx];
    __nv_bfloat16 hi = __float2bfloat16(x);
    __nv_bfloat16 lo = __float2bfloat16(x - __bfloat162float(hi));
    __nv_bfloat16* d = dst + (size_t)n * K3;
    d[k] = hi; d[DMODEL + k] = hi; d[2*DMODEL + k] = lo;
}

// ===========================================================================
// HMMA GEMM v2: C[M,N] = A'[M,3072] @ B'[N,3072]^T (+ residual)
// 128x128x64 CTA tile, 128 thr (4 warps 2x2, warp tile 64x64),
// 3-stage cp.async pipeline, smem stride 72 halfs.
// ===========================================================================
#define GTS 72
#define G_A_TILE (128*GTS)           // halfs per array
#define G_STAGE  (2*G_A_TILE)        // A+B halfs per stage
#define G_SMEM_BYTES (3*G_STAGE*2)   // 110592

template<bool RES>
__global__ __launch_bounds__(128) void gemm_mma_kernel(
    const __nv_bfloat16* __restrict__ A, const __nv_bfloat16* __restrict__ Bw,
    const float* __restrict__ Rsd, float* __restrict__ C, int N)
{
    extern __shared__ __nv_bfloat16 gs[];
    int tid = threadIdx.x, lid = tid & 31, wid = tid >> 5;
    int wm = (wid & 1) * 64;
    int wn = (wid >> 1) * 64;
    int m0 = blockIdx.y * 128, n0 = blockIdx.x * 128;

    const char* gA = (const char*)(A  + (size_t)(m0 + tid) * K3);
    const char* gB = (const char*)(Bw + (size_t)(n0 + tid) * K3);

    auto prefetch = [&](int c) {
        int s = c % 3;
        uint32_t da = smem_u32(gs + s * G_STAGE + tid * GTS);
        uint32_t db = smem_u32(gs + s * G_STAGE + G_A_TILE + tid * GTS);
        const char* a = gA + (size_t)c * 128;
        const char* b = gB + (size_t)c * 128;
#pragma unroll
        for (int i = 0; i < 8; i++) {
            cp16(da + i*16, a + i*16);
            cp16(db + i*16, b + i*16);
        }
        cp_commit();
    };

    float acc[4][8][4] = {};

    prefetch(0); prefetch(1); prefetch(2);

    int g  = lid >> 3, r8 = lid & 7;
    int a_m = wm + (g & 1) * 8 + r8;
    int a_k = (g >> 1) * 8;
    int b_n = wn + (g >> 1) * 8 + r8;
    int b_k = (g & 1) * 8;

    for (int kt = 0; kt < NKT; kt++) {
        int s = kt % 3;
        if (kt < NKT - 2) cp_wait<2>();
        else if (kt == NKT - 2) cp_wait<1>();
        else cp_wait<0>();
        __syncthreads();

        uint32_t baseA = smem_u32(gs + s * G_STAGE);
        uint32_t baseB = baseA + G_A_TILE * 2;
#pragma unroll
        for (int ks = 0; ks < 4; ks++) {
            uint32_t a[4][4], b[8][2];
#pragma unroll
            for (int mt = 0; mt < 4; mt++) {
                uint32_t addr = baseA + (uint32_t)((a_m + mt*16) * GTS + ks*16 + a_k) * 2u;
                ldsm4(a[mt][0], a[mt][1], a[mt][2], a[mt][3], addr);
            }
#pragma unroll
            for (int nt = 0; nt < 4; nt++) {
                uint32_t r0, r1, r2, r3;
                uint32_t addr = baseB + (uint32_t)((b_n + nt*16) * GTS + ks*16 + b_k) * 2u;
                ldsm4(r0, r1, r2, r3, addr);
                b[nt*2][0] = r0;   b[nt*2][1] = r1;
                b[nt*2+1][0] = r2; b[nt*2+1][1] = r3;
            }
#pragma unroll
            for (int mt = 0; mt < 4; mt++)
#pragma unroll
                for (int nn = 0; nn < 8; nn++)
                    mma16816(acc[mt][nn], a[mt], b[nn]);
        }
        __syncthreads();
        if (kt + 3 < NKT) prefetch(kt + 3);
    }

    int row = lid >> 2, col = (lid & 3) * 2;
#pragma unroll
    for (int mt = 0; mt < 4; mt++) {
#pragma unroll
        for (int nn = 0; nn < 8; nn++) {
            int m = m0 + wm + mt*16 + row;
            int n = n0 + wn + nn*8 + col;
            float2 v0 = make_float2(acc[mt][nn][0], acc[mt][nn][1]);
            float2 v1 = make_float2(acc[mt][nn][2], acc[mt][nn][3]);
            if (RES) {
                float2 q0 = *(const float2*)(Rsd + (size_t)m * N + n);
                float2 q1 = *(const float2*)(Rsd + (size_t)(m+8) * N + n);
                v0.x += q0.x; v0.y += q0.y;
                v1.x += q1.x; v1.y += q1.y;
            }
            *(float2*)(C + (size_t)m * N + n)     = v0;
            *(float2*)(C + (size_t)(m+8) * N + n) = v1;
        }
    }
}

// ===========================================================================
// K3: RoPE + fp32->bf16 hi/lo split into head-major arrays.
// ===========================================================================
__global__ void rope_split_kernel() {
    int idx = blockIdx.x * 256 + threadIdx.x;
    int d = idx & 31;
    int h = (idx >> 5) & 15;
    int ms = idx >> 9;            // m*3 + s
    int s = ms % 3;
    int m = ms / 3;
    int t = m & (SEQ - 1);
    int b = m >> 11;
    const float* src = g_qkv + (size_t)m * EDIM + s * DMODEL + h * HDIM;
    float f1 = src[d], f2 = src[d + 32];
    float y1, y2;
    if (s < 2) {
        float inv_freq = powf(10000.0f, -(float)d * (1.0f / 32.0f));
        float ang = (float)t * inv_freq;
        float sn, cs;
        sincosf(ang, &sn, &cs);
        y1 = f1 * cs - f2 * sn;
        y2 = f2 * cs + f1 * sn;
        if (s == 0) { y1 *= 0.125f; y2 *= 0.125f; }
    } else { y1 = f1; y2 = f2; }
    size_t base = (size_t)(s * 2) * SEC_ELEMS + ((size_t)(b * NHEADS + h) * SEQ + t) * HDIM;
    __nv_bfloat16 h1 = __float2bfloat16(y1);
    __nv_bfloat16 h2 = __float2bfloat16(y2);
    g_split[base + d]      = h1;
    g_split[base + d + 32] = h2;
    size_t lb = base + SEC_ELEMS;
    g_split[lb + d]      = __float2bfloat16(y1 - __bfloat162float(h1));
    g_split[lb + d + 32] = __float2bfloat16(y2 - __bfloat162float(h2));
}

// ===========================================================================
// K4: HMMA causal flash attention, split-bf16, Br=128 (8 warps), Bc=64.
// grid (SEQ/128, NHEADS, BATCH), 256 threads. Output -> split-A' in g_abf.
// ===========================================================================
#define ATS 72
#define QT_TILE (128*ATS)
#define KT_TILE (64*ATS)
#define ATT_SMEM ((2*QT_TILE + 8*KT_TILE) * 2)   // 110592 bytes

__global__ __launch_bounds__(256) void attn_mma_kernel() {
    extern __shared__ __nv_bfloat16 sh[];
    __nv_bfloat16* Qh = sh;
    __nv_bfloat16* Ql = sh + QT_TILE;
    __nv_bfloat16* KV = sh + 2 * QT_TILE;   // stage s: +s*4*KT_TILE; [Khi,Klo,Vhi,Vlo]

    int qt = blockIdx.x, hh = blockIdx.y, b = blockIdx.z;
    int bh = b * NHEADS + hh;
    int tid = threadIdx.x;
    int lid = tid & 31, wid = tid >> 5;
    int q0 = qt * 128;

    const __nv_bfloat16* gqh = g_split + 0*SEC_ELEMS + (size_t)bh * SEQ * HDIM;
    const __nv_bfloat16* gql = g_split + 1*SEC_ELEMS + (size_t)bh * SEQ * HDIM;
    const __nv_bfloat16* gkh = g_split + 2*SEC_ELEMS + (size_t)bh * SEQ * HDIM;
    const __nv_bfloat16* gkl = g_split + 3*SEC_ELEMS + (size_t)bh * SEQ * HDIM;
    const __nv_bfloat16* gvh = g_split + 4*SEC_ELEMS + (size_t)bh * SEQ * HDIM;
    const __nv_bfloat16* gvl = g_split + 5*SEC_ELEMS + (size_t)bh * SEQ * HDIM;

    // Q load: 128 rows, thread pair per row
    {
        int ldrow = tid >> 1;
        int ldh   = (tid & 1) * 32;
        const __nv_bfloat16* s0 = gqh + (size_t)(q0 + ldrow) * HDIM + ldh;
        const __nv_bfloat16* s1 = gql + (size_t)(q0 + ldrow) * HDIM + ldh;
        uint32_t d0 = smem_u32(Qh + ldrow * ATS + ldh);
        uint32_t d1 = smem_u32(Ql + ldrow * ATS + ldh);
#pragma unroll
        for (int i = 0; i < 4; i++) {
            cp16(d0 + i*16, s0 + i*8);
            cp16(d1 + i*16, s1 + i*8);
        }
    }

    int kvrow = tid >> 2;            // 0..63
    int kvh   = (tid & 3) * 16;      // halfs
    auto prefetch = [&](int kt) {
        int s = kt & 1;
        __nv_bfloat16* base = KV + s * 4 * KT_TILE;
        size_t gr = (size_t)(kt * 64 + kvrow) * HDIM + kvh;
        const __nv_bfloat16* srcs[4] = { gkh + gr, gkl + gr, gvh + gr, gvl + gr };
#pragma unroll
        for (int a = 0; a < 4; a++) {
            uint32_t dst = smem_u32(base + a * KT_TILE + kvrow * ATS + kvh);
            cp16(dst, srcs[a]);
            cp16(dst + 16, srcs[a] + 8);
        }
        cp_commit();
    };
    prefetch(0);   // group 0 = Q + tile 0

    float m0 = -1e30f, m1 = -1e30f, l0 = 0.f, l1 = 0.f;
    float oacc[8][4] = {};

    int g  = lid >> 3, r8 = lid & 7;
    int a_row = wid * 16 + (g & 1) * 8 + r8;
    int a_kof = (g >> 1) * 8;
    int b_row = (g >> 1) * 8 + r8;
    int b_kof = (g & 1) * 8;
    int v_row = lid & 15;
    int v_col = (lid >> 4) * 8;
    int qrow_loc = wid * 16 + (lid >> 2);
    int row_g = q0 + qrow_loc;

    int ntiles = 2 * qt + 2;
    for (int kt = 0; kt < ntiles; kt++) {
        __syncthreads();
        if (kt + 1 < ntiles) { prefetch(kt + 1); cp_wait<1>(); } else { cp_wait<0>(); }
        __syncthreads();

        const __nv_bfloat16* Khp = KV + (kt & 1) * 4 * KT_TILE;
        uint32_t bKh = smem_u32(Khp);
        uint32_t bKl = bKh + KT_TILE * 2;
        uint32_t bVh = bKl + KT_TILE * 2;
        uint32_t bVl = bVh + KT_TILE * 2;
        uint32_t bQh = smem_u32(Qh), bQl = smem_u32(Ql);

        // ---- S = Q K^T (split-3) ----
        float sacc[8][4] = {};
#pragma unroll
        for (int kc = 0; kc < 4; kc++) {
            uint32_t ah[4], al[4];
            uint32_t aoff = (uint32_t)(a_row * ATS + kc*16 + a_kof) * 2u;
            ldsm4(ah[0], ah[1], ah[2], ah[3], bQh + aoff);
            ldsm4(al[0], al[1], al[2], al[3], bQl + aoff);
            uint32_t bhf[8][2], blf[8][2];
#pragma unroll
            for (int p = 0; p < 4; p++) {
                uint32_t boff = (uint32_t)((p*16 + b_row) * ATS + kc*16 + b_kof) * 2u;
                uint32_t r0, r1, r2, r3;
                ldsm4(r0, r1, r2, r3, bKh + boff);
                bhf[2*p][0] = r0; bhf[2*p][1] = r1;
                bhf[2*p+1][0] = r2; bhf[2*p+1][1] = r3;
                ldsm4(r0, r1, r2, r3, bKl + boff);
                blf[2*p][0] = r0; blf[2*p][1] = r1;
                blf[2*p+1][0] = r2; blf[2*p+1][1] = r3;
            }
#pragma unroll
            for (int j = 0; j < 8; j++) {
                mma16816(sacc[j], ah, bhf[j]);
                mma16816(sacc[j], al, bhf[j]);
                mma16816(sacc[j], ah, blf[j]);
            }
        }

        // ---- causal mask (only the last two tiles can cross the diagonal) ----
        if (kt >= 2 * qt) {
#pragma unroll
            for (int j = 0; j < 8; j++) {
                int col_g = kt*64 + j*8 + (lid & 3) * 2;
                if (col_g     > row_g)     sacc[j][0] = -1e30f;
                if (col_g + 1 > row_g)     sacc[j][1] = -1e30f;
                if (col_g     > row_g + 8) sacc[j][2] = -1e30f;
                if (col_g + 1 > row_g + 8) sacc[j][3] = -1e30f;
            }
        }

        // ---- online softmax ----
        float mx0 = -1e30f, mx1 = -1e30f;
#pragma unroll
        for (int j = 0; j < 8; j++) {
            mx0 = fmaxf(mx0, fmaxf(sacc[j][0], sacc[j][1]));
            mx1 = fmaxf(mx1, fmaxf(sacc[j][2], sacc[j][3]));
        }
        mx0 = fmaxf(mx0, __shfl_xor_sync(0xffffffffu, mx0, 1));
        mx0 = fmaxf(mx0, __shfl_xor_sync(0xffffffffu, mx0, 2));
        mx1 = fmaxf(mx1, __shfl_xor_sync(0xffffffffu, mx1, 1));
        mx1 = fmaxf(mx1, __shfl_xor_sync(0xffffffffu, mx1, 2));
        float mn0 = fmaxf(m0, mx0), mn1 = fmaxf(m1, mx1);
        float al0 = __expf(m0 - mn0), al1 = __expf(m1 - mn1);
        float s0 = 0.f, s1 = 0.f;
#pragma unroll
        for (int j = 0; j < 8; j++) {
            sacc[j][0] = __expf(sacc[j][0] - mn0);
            sacc[j][1] = __expf(sacc[j][1] - mn0);
            sacc[j][2] = __expf(sacc[j][2] - mn1);
            sacc[j][3] = __expf(sacc[j][3] - mn1);
            s0 += sacc[j][0] + sacc[j][1];
            s1 += sacc[j][2] + sacc[j][3];
        }
        s0 += __shfl_xor_sync(0xffffffffu, s0, 1);
        s0 += __shfl_xor_sync(0xffffffffu, s0, 2);
        s1 += __shfl_xor_sync(0xffffffffu, s1, 1);
        s1 += __shfl_xor_sync(0xffffffffu, s1, 2);
        l0 = l0 * al0 + s0;  l1 = l1 * al1 + s1;
        m0 = mn0;  m1 = mn1;
#pragma unroll
        for (int j = 0; j < 8; j++) {
            oacc[j][0] *= al0; oacc[j][1] *= al0;
            oacc[j][2] *= al1; oacc[j][3] *= al1;
        }

        // ---- split P fragments ----
        uint32_t ph01[8], ph23[8], pl01[8], pl23[8];
#pragma unroll
        for (int j = 0; j < 8; j++) {
            float p0 = sacc[j][0], p1 = sacc[j][1], p2 = sacc[j][2], p3 = sacc[j][3];
            __nv_bfloat16 h0 = __float2bfloat16(p0), h1 = __float2bfloat16(p1);
            __nv_bfloat16 h2 = __float2bfloat16(p2), h3 = __float2bfloat16(p3);
            ph01[j] = ((uint32_t)*(uint16_t*)&h1 << 16) | *(uint16_t*)&h0;
            ph23[j] = ((uint32_t)*(uint16_t*)&h3 << 16) | *(uint16_t*)&h2;
            pl01[j] = pack_bf16(p0 - __bfloat162float(h0), p1 - __bfloat162float(h1));
            pl23[j] = pack_bf16(p2 - __bfloat162float(h2), p3 - __bfloat162float(h3));
        }

        // ---- O += P V (split-3), V via ldmatrix.trans ----
#pragma unroll
        for (int kc = 0; kc < 4; kc++) {
            uint32_t aH[4] = { ph01[2*kc], ph23[2*kc], ph01[2*kc+1], ph23[2*kc+1] };
            uint32_t aL[4] = { pl01[2*kc], pl23[2*kc], pl01[2*kc+1], pl23[2*kc+1] };
#pragma unroll
            for (int p = 0; p < 4; p++) {
                uint32_t voff = (uint32_t)((kc*16 + v_row) * ATS + p*16 + v_col) * 2u;
                uint32_t h0, h1, h2, h3, l0r, l1r, l2r, l3r;
                ldsm4t(h0, h1, h2, h3, bVh + voff);
                ldsm4t(l0r, l1r, l2r, l3r, bVl + voff);
                uint32_t bv0[2] = { h0, h1 }, bv1[2] = { h2, h3 };
                uint32_t bw0[2] = { l0r, l1r }, bw1[2] = { l2r, l3r };
                mma16816(oacc[2*p],   aH, bv0);
                mma16816(oacc[2*p],   aL, bv0);
                mma16816(oacc[2*p],   aH, bw0);
                mma16816(oacc[2*p+1], aH, bv1);
                mma16816(oacc[2*p+1], aL, bv1);
                mma16816(oacc[2*p+1], aH, bw1);
            }
        }
    }

    // ---- epilogue: normalize, write split-A' into g_abf ----
    float inv0 = 1.0f / l0, inv1 = 1.0f / l1;
    int mg0 = b * SEQ + q0 + qrow_loc;
    int mg1 = mg0 + 8;
#pragma unroll
    for (int j = 0; j < 8; j++) {
        int col = hh * HDIM + j*8 + (lid & 3) * 2;
        float v0 = oacc[j][0] * inv0, v1 = oacc[j][1] * inv0;
        float v2 = oacc[j][2] * inv1, v3 = oacc[j][3] * inv1;
        __nv_bfloat16 h0 = __float2bfloat16(v0), h1 = __float2bfloat16(v1);
        __nv_bfloat16 h2 = __float2bfloat16(v2), h3 = __float2bfloat16(v3);
        __nv_bfloat162 hp0; hp0.x = h0; hp0.y = h1;
        __nv_bfloat162 hp1; hp1.x = h2; hp1.y = h3;
        __nv_bfloat162 lp0; lp0.x = __float2bfloat16(v0 - __bfloat162float(h0));
                            lp0.y = __float2bfloat16(v1 - __bfloat162float(h1));
        __nv_bfloat162 lp1; lp1.x = __float2bfloat16(v2 - __bfloat162float(h2));
                            lp1.y = __float2bfloat16(v3 - __bfloat162float(h3));
        __nv_bfloat16* r0p = g_abf + (size_t)mg0 * K3 + col;
        __nv_bfloat16* r1p = g_abf + (size_t)mg1 * K3 + col;
        *(__nv_bfloat162*)(r0p)              = hp0;
        *(__nv_bfloat162*)(r0p + DMODEL)     = lp0;
        *(__nv_bfloat162*)(r0p + 2*DMODEL)   = hp0;
        *(__nv_bfloat162*)(r1p)              = hp1;
        *(__nv_bfloat162*)(r1p + DMODEL)     = lp1;
        *(__nv_bfloat162*)(r1p + 2*DMODEL)   = hp1;
    }
}

// ===========================================================================
extern "C" void kernel_launch(void* const* d_in, const int* in_sizes, int n_in,
                              void* d_out, int out_size) {
    const float* x      = (const float*)d_in[0];
    const float* norm_w = (const float*)d_in[1];
    const float* w_qkv  = (const float*)d_in[2];
    const float* w_out  = (const float*)d_in[3];
    float* out = (float*)d_out;

    __nv_bfloat16 *p_abf, *p_bbf, *p_bbf2;
    float *p_qkv;
    cudaGetSymbolAddress((void**)&p_abf,  g_abf);
    cudaGetSymbolAddress((void**)&p_bbf,  g_bbf);
    cudaGetSymbolAddress((void**)&p_bbf2, g_bbf2);
    cudaGetSymbolAddress((void**)&p_qkv,  g_qkv);

    cudaFuncSetAttribute(gemm_mma_kernel<false>,
                         cudaFuncAttributeMaxDynamicSharedMemorySize, G_SMEM_BYTES);
    cudaFuncSetAttribute(gemm_mma_kernel<true>,
                         cudaFuncAttributeMaxDynamicSharedMemorySize, G_SMEM_BYTES);
    cudaFuncSetAttribute(attn_mma_kernel,
                         cudaFuncAttributeMaxDynamicSharedMemorySize, ATT_SMEM);

    // 1. RMSNorm -> A'
    rmsnorm_kernel<<<MROWS, 256>>>(x, norm_w);

    // 2. w_qkv -> B'
    convert_w_kernel<<<(EDIM*DMODEL)/256, 256>>>(w_qkv, p_bbf, EDIM*DMODEL);

    // 3. QKV projection (HMMA)
    gemm_mma_kernel<false><<<dim3(EDIM/128, MROWS/128), 128, G_SMEM_BYTES>>>(
        p_abf, p_bbf, nullptr, p_qkv, EDIM);

    // 4. RoPE + split into head-major bf16 hi/lo
    rope_split_kernel<<<(MROWS * 3 * NHEADS * 32) / 256, 256>>>();

    // 5. HMMA causal flash attention (Br=128)
    attn_mma_kernel<<<dim3(SEQ/128, NHEADS, BATCH), 256, ATT_SMEM>>>();

    // 6. w_out -> B'
    convert_w_kernel<<<(DMODEL*DMODEL)/256, 256>>>(w_out, p_bbf2, DMODEL*DMODEL);

    // 7. Output projection + residual (HMMA)
    gemm_mma_kernel<true><<<dim3(DMODEL/128, MROWS/128), 128, G_SMEM_BYTES>>>(
        p_abf, p_bbf2, x, out, DMODEL);
}

// round 6
// speedup vs baseline: 1.6759x; 1.6759x over previous
#include <cuda_runtime.h>
#include <cuda_fp16.h>
#include <math.h>
#include <stdint.h>

#define BATCH   2
#define SEQ     2048
#define DMODEL  1024
#define NHEADS  16
#define HDIM    64
#define MROWS   (BATCH*SEQ)        // 4096
#define EDIM    (3*DMODEL)         // 3072
#define K2      (2*DMODEL)         // expanded split-K = 2048
#define NK      (K2/32)            // 64 k-chunks of 32
#define BH      (BATCH*NHEADS)     // 32

// Scratch (device globals; no runtime allocation allowed)
__device__ __align__(128) __half g_abf[MROWS*K2];     // A' = [hi|lo]
__device__ __align__(128) __half g_bbf[EDIM*K2];      // B' = [Bh|Bh] for w_qkv
__device__ __align__(128) __half g_bbf2[DMODEL*K2];   // B' for w_out
__device__ float g_qkv[MROWS*EDIM];
// head-major fp16 q/k/v: [sec: qh, ql, kh, vh][bh][t][d]
__device__ __align__(128) __half g_split[(size_t)4*BH*SEQ*HDIM];
#define SEC_ELEMS ((size_t)BH*SEQ*HDIM)

// ===========================================================================
// helpers
// ===========================================================================
__device__ __forceinline__ uint32_t smem_u32(const void* p) {
    uint32_t a;
    asm("{ .reg .u64 t; cvta.to.shared.u64 t, %1; cvt.u32.u64 %0, t; }" : "=r"(a) : "l"(p));
    return a;
}
__device__ __forceinline__ void cp16(uint32_t smem, const void* g) {
    asm volatile("cp.async.cg.shared.global [%0], [%1], 16;" :: "r"(smem), "l"(g) : "memory");
}
__device__ __forceinline__ void cp_commit() {
    asm volatile("cp.async.commit_group;" ::: "memory");
}
template<int N> __device__ __forceinline__ void cp_wait() {
    asm volatile("cp.async.wait_group %0;" :: "n"(N) : "memory");
}
__device__ __forceinline__ void ldsm4(uint32_t& r0, uint32_t& r1, uint32_t& r2, uint32_t& r3,
                                      uint32_t addr) {
    asm volatile("ldmatrix.sync.aligned.m8n8.x4.shared.b16 {%0,%1,%2,%3}, [%4];"
                 : "=r"(r0), "=r"(r1), "=r"(r2), "=r"(r3) : "r"(addr));
}
__device__ __forceinline__ void ldsm4t(uint32_t& r0, uint32_t& r1, uint32_t& r2, uint32_t& r3,
                                       uint32_t addr) {
    asm volatile("ldmatrix.sync.aligned.m8n8.x4.trans.shared.b16 {%0,%1,%2,%3}, [%4];"
                 : "=r"(r0), "=r"(r1), "=r"(r2), "=r"(r3) : "r"(addr));
}
__device__ __forceinline__ void mma16816(float* d, const uint32_t* a, const uint32_t* b) {
    asm volatile("mma.sync.aligned.m16n8k16.row.col.f32.f16.f16.f32 "
                 "{%0,%1,%2,%3}, {%4,%5,%6,%7}, {%8,%9}, {%0,%1,%2,%3};"
                 : "+f"(d[0]), "+f"(d[1]), "+f"(d[2]), "+f"(d[3])
                 : "r"(a[0]), "r"(a[1]), "r"(a[2]), "r"(a[3]), "r"(b[0]), "r"(b[1]));
}
__device__ __forceinline__ uint32_t pack_f16(float a, float b) {
    __half2 t = __floats2half2_rn(a, b);
    return *(uint32_t*)&t;
}

// ===========================================================================
// K1: RMSNorm -> fp16-split A' = [hi|lo]. One block per row, 256 threads.
// ===========================================================================
__global__ void rmsnorm_kernel(const float* __restrict__ x, const float* __restrict__ w) {
    int row = blockIdx.x;
    int tid = threadIdx.x;
    const float* xr = x + (size_t)row * DMODEL;
    float v[4];
    float ss = 0.f;
#pragma unroll
    for (int i = 0; i < 4; i++) { v[i] = xr[tid + i*256]; ss += v[i]*v[i]; }
    __shared__ float red[256];
    red[tid] = ss;
    __syncthreads();
#pragma unroll
    for (int off = 128; off > 0; off >>= 1) {
        if (tid < off) red[tid] += red[tid + off];
        __syncthreads();
    }
    float inv = rsqrtf(red[0] * (1.0f / DMODEL) + 1e-6f);
    __half* d = g_abf + (size_t)row * K2;
#pragma unroll
    for (int i = 0; i < 4; i++) {
        int col = tid + i*256;
        float y = v[i] * inv * w[col];
        __half hi = __float2half_rn(y);
        d[col]          = hi;
        d[DMODEL + col] = __float2half_rn(y - __half2float(hi));
    }
}

// ===========================================================================
// Weight conversion: fp32 [rows,1024] -> fp16 duplicated [rows,2048] = [Bh|Bh]
// ===========================================================================
__global__ void convert_w_kernel(const float* __restrict__ src, __half* __restrict__ dst,
                                 int total) {
    int idx = blockIdx.x * 256 + threadIdx.x;
    if (idx >= total) return;
    int n = idx >> 10, k = idx & 1023;
    __half h = __float2half_rn(src[idx]);
    __half* d = dst + (size_t)n * K2;
    d[k] = h; d[DMODEL + k] = h;
}

// ===========================================================================
// HMMA GEMM (r4 structure, fp16, K=2048): C = A'B'^T (+res)
// 128x128x32 CTA tile, 256 thr (8 warps 2x4), warp tile 64x32, 2-stage.
// ===========================================================================
template<bool RES>
__global__ __launch_bounds__(256) void gemm_mma_kernel(
    const __half* __restrict__ A, const __half* __restrict__ Bw,
    const float* __restrict__ Rsd, float* __restrict__ C, int N)
{
    __shared__ __align__(128) __half sA[2][128*40];
    __shared__ __align__(128) __half sB[2][128*40];

    int tid = threadIdx.x, lid = tid & 31, wid = tid >> 5;
    int wm = (wid & 1) * 64;
    int wn = (wid >> 1) * 32;
    int m0 = blockIdx.y * 128, n0 = blockIdx.x * 128;

    int ldrow = tid >> 1;
    int ldcol = (tid & 1) * 32;       // bytes
    const char* gA = (const char*)(A  + (size_t)(m0 + ldrow) * K2) + ldcol;
    const char* gB = (const char*)(Bw + (size_t)(n0 + ldrow) * K2) + ldcol;

    auto prefetch = [&](int c) {
        int s = c & 1;
        uint32_t da = smem_u32(&sA[s][ldrow * 40]) + (uint32_t)ldcol;
        uint32_t db = smem_u32(&sB[s][ldrow * 40]) + (uint32_t)ldcol;
        const char* a = gA + (size_t)c * 64;
        const char* b = gB + (size_t)c * 64;
        cp16(da, a);      cp16(da + 16, a + 16);
        cp16(db, b);      cp16(db + 16, b + 16);
        cp_commit();
    };

    float acc[4][4][4] = {};

    prefetch(0); prefetch(1);

    int g  = lid >> 3, r8 = lid & 7;
    int a_m = wm + (g & 1) * 8 + r8;
    int a_k = (g >> 1) * 8;
    int b_n = wn + (g >> 1) * 8 + r8;
    int b_k = (g & 1) * 8;

    for (int kt = 0; kt < NK; kt++) {
        int s = kt & 1;
        if (kt + 1 < NK) cp_wait<1>(); else cp_wait<0>();
        __syncthreads();

        uint32_t baseA = smem_u32(&sA[s][0]);
        uint32_t baseB = smem_u32(&sB[s][0]);
#pragma unroll
        for (int ks = 0; ks < 2; ks++) {
            uint32_t a[4][4], b[4][2];
#pragma unroll
            for (int mt = 0; mt < 4; mt++) {
                uint32_t addr = baseA + (uint32_t)(a_m + mt*16) * 80u
                                      + (uint32_t)(a_k + ks*16) * 2u;
                ldsm4(a[mt][0], a[mt][1], a[mt][2], a[mt][3], addr);
            }
#pragma unroll
            for (int nt = 0; nt < 2; nt++) {
                uint32_t r0, r1, r2, r3;
                uint32_t addr = baseB + (uint32_t)(b_n + nt*16) * 80u
                                      + (uint32_t)(b_k + ks*16) * 2u;
                ldsm4(r0, r1, r2, r3, addr);
                b[nt*2][0] = r0;   b[nt*2][1] = r1;
                b[nt*2+1][0] = r2; b[nt*2+1][1] = r3;
            }
#pragma unroll
            for (int mt = 0; mt < 4; mt++)
#pragma unroll
                for (int nn = 0; nn < 4; nn++)
                    mma16816(acc[mt][nn], a[mt], b[nn]);
        }
        __syncthreads();
        if (kt + 2 < NK) prefetch(kt + 2);
    }

    int row = lid >> 2, col = (lid & 3) * 2;
#pragma unroll
    for (int mt = 0; mt < 4; mt++) {
#pragma unroll
        for (int nn = 0; nn < 4; nn++) {
            int m = m0 + wm + mt*16 + row;
            int n = n0 + wn + nn*8 + col;
            float2 v0 = make_float2(acc[mt][nn][0], acc[mt][nn][1]);
            float2 v1 = make_float2(acc[mt][nn][2], acc[mt][nn][3]);
            if (RES) {
                float2 q0 = *(const float2*)(Rsd + (size_t)m * N + n);
                float2 q1 = *(const float2*)(Rsd + (size_t)(m+8) * N + n);
                v0.x += q0.x; v0.y += q0.y;
                v1.x += q1.x; v1.y += q1.y;
            }
            *(float2*)(C + (size_t)m * N + n)     = v0;
            *(float2*)(C + (size_t)(m+8) * N + n) = v1;
        }
    }
}

// ===========================================================================
// K3: RoPE + fp32->fp16 split into head-major arrays.
// Q: hi+lo (secs 0,1). K: hi (sec 2). V: hi (sec 3). Q scaled by 0.125.
// ===========================================================================
__global__ void rope_split_kernel() {
    int idx = blockIdx.x * 256 + threadIdx.x;   // MROWS*3*16*32 total
    int d = idx & 31;
    int h = (idx >> 5) & 15;
    int ms = idx >> 9;            // m*3 + s
    int s = ms % 3;
    int m = ms / 3;
    int t = m & (SEQ - 1);
    int b = m >> 11;
    const float* src = g_qkv + (size_t)m * EDIM + s * DMODEL + h * HDIM;
    float f1 = src[d], f2 = src[d + 32];
    float y1, y2;
    if (s < 2) {
        float inv_freq = powf(10000.0f, -(float)d * (1.0f / 32.0f));
        float ang = (float)t * inv_freq;
        float sn, cs;
        sincosf(ang, &sn, &cs);
        y1 = f1 * cs - f2 * sn;
        y2 = f2 * cs + f1 * sn;
        if (s == 0) { y1 *= 0.125f; y2 *= 0.125f; }
    } else { y1 = f1; y2 = f2; }
    int sec = (s == 0) ? 0 : (s + 1);   // q->0, k->2, v->3
    size_t base = (size_t)sec * SEC_ELEMS + ((size_t)(b * NHEADS + h) * SEQ + t) * HDIM;
    __half h1 = __float2half_rn(y1);
    __half h2 = __float2half_rn(y2);
    g_split[base + d]      = h1;
    g_split[base + d + 32] = h2;
    if (s == 0) {   // Q lo part
        size_t lb = base + SEC_ELEMS;
        g_split[lb + d]      = __float2half_rn(y1 - __half2float(h1));
        g_split[lb + d + 32] = __float2half_rn(y2 - __half2float(h2));
    }
}

// ===========================================================================
// K4: HMMA causal flash attention, fp16 (Q 2-term split, K/V single),
// fp32 softmax. grid (SEQ/64, NHEADS, BATCH), 128 threads (4 warps).
// Output written in split-A' = [hi|lo] layout into g_abf.
// ===========================================================================
#define ATS 72                         // smem row stride in halfs
#define AT_TILE (64*ATS)               // one 64x64 array
#define ATT_SMEM ((2 + 4) * AT_TILE * 2)   // bytes = 55296

__global__ __launch_bounds__(128) void attn_mma_kernel() {
    extern __shared__ __half sh[];
    __half* Qh = sh;
    __half* Ql = sh + AT_TILE;
    __half* KV = sh + 2 * AT_TILE;   // stage s: +s*2*AT_TILE; [Kh, Vh]

    int qt = blockIdx.x, hh = blockIdx.y, b = blockIdx.z;
    int bh = b * NHEADS + hh;
    int tid = threadIdx.x;
    int lid = tid & 31, wid = tid >> 5;
    int q0 = qt * 64;

    const __half* gqh = g_split + 0*SEC_ELEMS + (size_t)bh * SEQ * HDIM;
    const __half* gql = g_split + 1*SEC_ELEMS + (size_t)bh * SEQ * HDIM;
    const __half* gkh = g_split + 2*SEC_ELEMS + (size_t)bh * SEQ * HDIM;
    const __half* gvh = g_split + 3*SEC_ELEMS + (size_t)bh * SEQ * HDIM;

    int ldrow = tid >> 1;          // 0..63
    int ldh   = (tid & 1) * 32;    // halfs offset within row

    // Q load (part of group 0)
    {
        const __half* s0 = gqh + (size_t)(q0 + ldrow) * HDIM + ldh;
        const __half* s1 = gql + (size_t)(q0 + ldrow) * HDIM + ldh;
        uint32_t d0 = smem_u32(Qh + ldrow * ATS + ldh);
        uint32_t d1 = smem_u32(Ql + ldrow * ATS + ldh);
#pragma unroll
        for (int i = 0; i < 4; i++) {
            cp16(d0 + i*16, s0 + i*8);
            cp16(d1 + i*16, s1 + i*8);
        }
    }

    auto prefetch = [&](int kt) {
        int s = kt & 1;
        __half* base = KV + s * 2 * AT_TILE;
        size_t gr = (size_t)(kt * 64 + ldrow) * HDIM + ldh;
        const __half* srcs[2] = { gkh + gr, gvh + gr };
#pragma unroll
        for (int a = 0; a < 2; a++) {
            uint32_t dst = smem_u32(base + a * AT_TILE + ldrow * ATS + ldh);
#pragma unroll
            for (int i = 0; i < 4; i++) cp16(dst + i*16, srcs[a] + i*8);
        }
        cp_commit();
    };
    prefetch(0);   // group 0 = Q + tile 0

    float m0 = -1e30f, m1 = -1e30f, l0 = 0.f, l1 = 0.f;
    float oacc[8][4] = {};

    int g  = lid >> 3, r8 = lid & 7;
    int a_row = wid * 16 + (g & 1) * 8 + r8;   // Q smem row
    int a_kof = (g >> 1) * 8;                  // + kc*16
    int b_row = (g >> 1) * 8 + r8;             // K smem row within 16-pair (+p*16)
    int b_kof = (g & 1) * 8;
    int v_row = lid & 15;                      // + kc*16
    int v_col = (lid >> 4) * 8;                // + p*16
    int qrow_loc = wid * 16 + (lid >> 2);      // local q row for c0/c1

    for (int kt = 0; kt <= qt; kt++) {
        __syncthreads();
        if (kt < qt) { prefetch(kt + 1); cp_wait<1>(); } else { cp_wait<0>(); }
        __syncthreads();

        uint32_t bKh = smem_u32(KV + (kt & 1) * 2 * AT_TILE);
        uint32_t bVh = bKh + AT_TILE * 2;
        uint32_t bQh = smem_u32(Qh), bQl = smem_u32(Ql);

        // ---- S = Q K^T (Q split 2-term, K single) ----
        float sacc[8][4] = {};
#pragma unroll
        for (int kc = 0; kc < 4; kc++) {
            uint32_t ah[4], al[4];
            uint32_t aoff = (uint32_t)(a_row * ATS + kc*16 + a_kof) * 2u;
            ldsm4(ah[0], ah[1], ah[2], ah[3], bQh + aoff);
            ldsm4(al[0], al[1], al[2], al[3], bQl + aoff);
            uint32_t bhf[8][2];
#pragma unroll
            for (int p = 0; p < 4; p++) {
                uint32_t boff = (uint32_t)((p*16 + b_row) * ATS + kc*16 + b_kof) * 2u;
                uint32_t r0, r1, r2, r3;
                ldsm4(r0, r1, r2, r3, bKh + boff);
                bhf[2*p][0] = r0; bhf[2*p][1] = r1;
                bhf[2*p+1][0] = r2; bhf[2*p+1][1] = r3;
            }
#pragma unroll
            for (int j = 0; j < 8; j++) {
                mma16816(sacc[j], ah, bhf[j]);
                mma16816(sacc[j], al, bhf[j]);
            }
        }

        // ---- causal mask on diagonal tile ----
        if (kt == qt) {
#pragma unroll
            for (int j = 0; j < 8; j++) {
                int col = j*8 + (lid & 3) * 2;
                if (col     > qrow_loc)     sacc[j][0] = -1e30f;
                if (col + 1 > qrow_loc)     sacc[j][1] = -1e30f;
                if (col     > qrow_loc + 8) sacc[j][2] = -1e30f;
                if (col + 1 > qrow_loc + 8) sacc[j][3] = -1e30f;
            }
        }

        // ---- online softmax (rows qrow_loc and +8) ----
        float mx0 = -1e30f, mx1 = -1e30f;
#pragma unroll
        for (int j = 0; j < 8; j++) {
            mx0 = fmaxf(mx0, fmaxf(sacc[j][0], sacc[j][1]));
            mx1 = fmaxf(mx1, fmaxf(sacc[j][2], sacc[j][3]));
        }
        mx0 = fmaxf(mx0, __shfl_xor_sync(0xffffffffu, mx0, 1));
        mx0 = fmaxf(mx0, __shfl_xor_sync(0xffffffffu, mx0, 2));
        mx1 = fmaxf(mx1, __shfl_xor_sync(0xffffffffu, mx1, 1));
        mx1 = fmaxf(mx1, __shfl_xor_sync(0xffffffffu, mx1, 2));
        float mn0 = fmaxf(m0, mx0), mn1 = fmaxf(m1, mx1);
        float al0 = __expf(m0 - mn0), al1 = __expf(m1 - mn1);
        float s0 = 0.f, s1 = 0.f;
#pragma unroll
        for (int j = 0; j < 8; j++) {
            sacc[j][0] = __expf(sacc[j][0] - mn0);
            sacc[j][1] = __expf(sacc[j][1] - mn0);
            sacc[j][2] = __expf(sacc[j][2] - mn1);
            sacc[j][3] = __expf(sacc[j][3] - mn1);
            s0 += sacc[j][0] + sacc[j][1];
            s1 += sacc[j][2] + sacc[j][3];
        }
        s0 += __shfl_xor_sync(0xffffffffu, s0, 1);
        s0 += __shfl_xor_sync(0xffffffffu, s0, 2);
        s1 += __shfl_xor_sync(0xffffffffu, s1, 1);
        s1 += __shfl_xor_sync(0xffffffffu, s1, 2);
        l0 = l0 * al0 + s0;  l1 = l1 * al1 + s1;
        m0 = mn0;  m1 = mn1;
#pragma unroll
        for (int j = 0; j < 8; j++) {
            oacc[j][0] *= al0; oacc[j][1] *= al0;
            oacc[j][2] *= al1; oacc[j][3] *= al1;
        }

        // ---- split P fragments (fp16 hi + lo) ----
        uint32_t ph01[8], ph23[8], pl01[8], pl23[8];
#pragma unroll
        for (int j = 0; j < 8; j++) {
            float p0 = sacc[j][0], p1 = sacc[j][1], p2 = sacc[j][2], p3 = sacc[j][3];
            __half h0 = __float2half_rn(p0), h1 = __float2half_rn(p1);
            __half h2 = __float2half_rn(p2), h3 = __float2half_rn(p3);
            ph01[j] = ((uint32_t)*(uint16_t*)&h1 << 16) | *(uint16_t*)&h0;
            ph23[j] = ((uint32_t)*(uint16_t*)&h3 << 16) | *(uint16_t*)&h2;
            pl01[j] = pack_f16(p0 - __half2float(h0), p1 - __half2float(h1));
            pl23[j] = pack_f16(p2 - __half2float(h2), p3 - __half2float(h3));
        }

        // ---- O += P V (P split 2-term, V single), V via ldmatrix.trans ----
#pragma unroll
        for (int kc = 0; kc < 4; kc++) {
            uint32_t aH[4] = { ph01[2*kc], ph23[2*kc], ph01[2*kc+1], ph23[2*kc+1] };
            uint32_t aL[4] = { pl01[2*kc], pl23[2*kc], pl01[2*kc+1], pl23[2*kc+1] };
#pragma unroll
            for (int p = 0; p < 4; p++) {
                uint32_t voff = (uint32_t)((kc*16 + v_row) * ATS + p*16 + v_col) * 2u;
                uint32_t h0, h1, h2, h3;
                ldsm4t(h0, h1, h2, h3, bVh + voff);
                uint32_t bv0[2] = { h0, h1 }, bv1[2] = { h2, h3 };
                mma16816(oacc[2*p],   aH, bv0);
                mma16816(oacc[2*p],   aL, bv0);
                mma16816(oacc[2*p+1], aH, bv1);
                mma16816(oacc[2*p+1], aL, bv1);
            }
        }
    }

    // ---- epilogue: normalize, write split-A' = [hi|lo] into g_abf ----
    float inv0 = 1.0f / l0, inv1 = 1.0f / l1;
    int mg0 = b * SEQ + q0 + qrow_loc;
    int mg1 = mg0 + 8;
#pragma unroll
    for (int j = 0; j < 8; j++) {
        int col = hh * HDIM + j*8 + (lid & 3) * 2;
        float v0 = oacc[j][0] * inv0, v1 = oacc[j][1] * inv0;
        float v2 = oacc[j][2] * inv1, v3 = oacc[j][3] * inv1;
        __half h0 = __float2half_rn(v0), h1 = __float2half_rn(v1);
        __half h2 = __float2half_rn(v2), h3 = __float2half_rn(v3);
        __half2 hp0; hp0.x = h0; hp0.y = h1;
        __half2 hp1; hp1.x = h2; hp1.y = h3;
        __half2 lp0; lp0.x = __float2half_rn(v0 - __half2float(h0));
                     lp0.y = __float2half_rn(v1 - __half2float(h1));
        __half2 lp1; lp1.x = __float2half_rn(v2 - __half2float(h2));
                     lp1.y = __float2half_rn(v3 - __half2float(h3));
        __half* r0p = g_abf + (size_t)mg0 * K2 + col;
        __half* r1p = g_abf + (size_t)mg1 * K2 + col;
        *(__half2*)(r0p)          = hp0;
        *(__half2*)(r0p + DMODEL) = lp0;
        *(__half2*)(r1p)          = hp1;
        *(__half2*)(r1p + DMODEL) = lp1;
    }
}

// ===========================================================================
extern "C" void kernel_launch(void* const* d_in, const int* in_sizes, int n_in,
                              void* d_out, int out_size) {
    const float* x      = (const float*)d_in[0];
    const float* norm_w = (const float*)d_in[1];
    const float* w_qkv  = (const float*)d_in[2];
    const float* w_out  = (const float*)d_in[3];
    float* out = (float*)d_out;

    __half *p_abf, *p_bbf, *p_bbf2;
    float *p_qkv;
    cudaGetSymbolAddress((void**)&p_abf,  g_abf);
    cudaGetSymbolAddress((void**)&p_bbf,  g_bbf);
    cudaGetSymbolAddress((void**)&p_bbf2, g_bbf2);
    cudaGetSymbolAddress((void**)&p_qkv,  g_qkv);

    cudaFuncSetAttribute(attn_mma_kernel,
                         cudaFuncAttributeMaxDynamicSharedMemorySize, ATT_SMEM);

    // 1. RMSNorm -> A'
    rmsnorm_kernel<<<MROWS, 256>>>(x, norm_w);

    // 2. w_qkv -> B'
    convert_w_kernel<<<(EDIM*DMODEL)/256, 256>>>(w_qkv, p_bbf, EDIM*DMODEL);

    // 3. QKV projection (HMMA fp16, K=2048)
    gemm_mma_kernel<false><<<dim3(EDIM/128, MROWS/128), 256>>>(
        p_abf, p_bbf, nullptr, p_qkv, EDIM);

    // 4. RoPE + split into head-major fp16
    rope_split_kernel<<<(MROWS * 3 * NHEADS * 32) / 256, 256>>>();

    // 5. HMMA causal flash attention
    attn_mma_kernel<<<dim3(SEQ/64, NHEADS, BATCH), 128, ATT_SMEM>>>();

    // 6. w_out -> B'
    convert_w_kernel<<<(DMODEL*DMODEL)/256, 256>>>(w_out, p_bbf2, DMODEL*DMODEL);

    // 7. Output projection + residual (HMMA fp16)
    gemm_mma_kernel<true><<<dim3(DMODEL/128, MROWS/128), 256>>>(
        p_abf, p_bbf2, x, out, DMODEL);
}

// round 7
// speedup vs baseline: 2.7204x; 1.6233x over previous
#include <cuda_runtime.h>
#include <cuda_fp16.h>
#include <math.h>
#include <stdint.h>

#define BATCH   2
#define SEQ     2048
#define DMODEL  1024
#define NHEADS  16
#define HDIM    64
#define MROWS   (BATCH*SEQ)        // 4096
#define EDIM    (3*DMODEL)         // 3072
#define KD      DMODEL             // GEMM K = 1024
#define NK      (KD/32)            // 32 k-chunks of 32
#define BH      (BATCH*NHEADS)     // 32

// Scratch (device globals; no runtime allocation allowed)
__device__ __align__(128) __half g_abf[MROWS*KD];      // fp16 activations (h, then attn-out)
__device__ __align__(128) __half g_bbf[EDIM*KD];       // fp16 w_qkv
__device__ __align__(128) __half g_bbf2[DMODEL*KD];    // fp16 w_out
__device__ float g_qkv[MROWS*EDIM];
// head-major fp16 q/k/v: [sec: q, k, v][bh][t][d]
__device__ __align__(128) __half g_split[(size_t)3*BH*SEQ*HDIM];
#define SEC_ELEMS ((size_t)BH*SEQ*HDIM)

// ===========================================================================
// helpers
// ===========================================================================
__device__ __forceinline__ uint32_t smem_u32(const void* p) {
    uint32_t a;
    asm("{ .reg .u64 t; cvta.to.shared.u64 t, %1; cvt.u32.u64 %0, t; }" : "=r"(a) : "l"(p));
    return a;
}
__device__ __forceinline__ void cp16(uint32_t smem, const void* g) {
    asm volatile("cp.async.cg.shared.global [%0], [%1], 16;" :: "r"(smem), "l"(g) : "memory");
}
__device__ __forceinline__ void cp_commit() {
    asm volatile("cp.async.commit_group;" ::: "memory");
}
template<int N> __device__ __forceinline__ void cp_wait() {
    asm volatile("cp.async.wait_group %0;" :: "n"(N) : "memory");
}
__device__ __forceinline__ void ldsm4(uint32_t& r0, uint32_t& r1, uint32_t& r2, uint32_t& r3,
                                      uint32_t addr) {
    asm volatile("ldmatrix.sync.aligned.m8n8.x4.shared.b16 {%0,%1,%2,%3}, [%4];"
                 : "=r"(r0), "=r"(r1), "=r"(r2), "=r"(r3) : "r"(addr));
}
__device__ __forceinline__ void ldsm4t(uint32_t& r0, uint32_t& r1, uint32_t& r2, uint32_t& r3,
                                       uint32_t addr) {
    asm volatile("ldmatrix.sync.aligned.m8n8.x4.trans.shared.b16 {%0,%1,%2,%3}, [%4];"
                 : "=r"(r0), "=r"(r1), "=r"(r2), "=r"(r3) : "r"(addr));
}
__device__ __forceinline__ void mma16816(float* d, const uint32_t* a, const uint32_t* b) {
    asm volatile("mma.sync.aligned.m16n8k16.row.col.f32.f16.f16.f32 "
                 "{%0,%1,%2,%3}, {%4,%5,%6,%7}, {%8,%9}, {%0,%1,%2,%3};"
                 : "+f"(d[0]), "+f"(d[1]), "+f"(d[2]), "+f"(d[3])
                 : "r"(a[0]), "r"(a[1]), "r"(a[2]), "r"(a[3]), "r"(b[0]), "r"(b[1]));
}

// ===========================================================================
// K1: RMSNorm -> fp16. One block per row, 256 threads.
// ===========================================================================
__global__ void rmsnorm_kernel(const float* __restrict__ x, const float* __restrict__ w) {
    int row = blockIdx.x;
    int tid = threadIdx.x;
    const float* xr = x + (size_t)row * DMODEL;
    float v[4];
    float ss = 0.f;
#pragma unroll
    for (int i = 0; i < 4; i++) { v[i] = xr[tid + i*256]; ss += v[i]*v[i]; }
    __shared__ float red[256];
    red[tid] = ss;
    __syncthreads();
#pragma unroll
    for (int off = 128; off > 0; off >>= 1) {
        if (tid < off) red[tid] += red[tid + off];
        __syncthreads();
    }
    float inv = rsqrtf(red[0] * (1.0f / DMODEL) + 1e-6f);
    __half* d = g_abf + (size_t)row * KD;
#pragma unroll
    for (int i = 0; i < 4; i++) {
        int col = tid + i*256;
        d[col] = __float2half_rn(v[i] * inv * w[col]);
    }
}

// ===========================================================================
// Weight conversion: fp32 -> fp16, elementwise.
// ===========================================================================
__global__ void convert_w_kernel(const float* __restrict__ src, __half* __restrict__ dst,
                                 int total) {
    int idx = blockIdx.x * 256 + threadIdx.x;
    if (idx >= total) return;
    dst[idx] = __float2half_rn(src[idx]);
}

// ===========================================================================
// HMMA GEMM (fp16, K=1024): C = A B^T (+res)
// 128x128x32 CTA tile, 256 thr (8 warps 2x4), warp tile 64x32, 2-stage.
// ===========================================================================
template<bool RES>
__global__ __launch_bounds__(256) void gemm_mma_kernel(
    const __half* __restrict__ A, const __half* __restrict__ Bw,
    const float* __restrict__ Rsd, float* __restrict__ C, int N)
{
    __shared__ __align__(128) __half sA[2][128*40];
    __shared__ __align__(128) __half sB[2][128*40];

    int tid = threadIdx.x, lid = tid & 31, wid = tid >> 5;
    int wm = (wid & 1) * 64;
    int wn = (wid >> 1) * 32;
    int m0 = blockIdx.y * 128, n0 = blockIdx.x * 128;

    int ldrow = tid >> 1;
    int ldcol = (tid & 1) * 32;       // bytes
    const char* gA = (const char*)(A  + (size_t)(m0 + ldrow) * KD) + ldcol;
    const char* gB = (const char*)(Bw + (size_t)(n0 + ldrow) * KD) + ldcol;

    auto prefetch = [&](int c) {
        int s = c & 1;
        uint32_t da = smem_u32(&sA[s][ldrow * 40]) + (uint32_t)ldcol;
        uint32_t db = smem_u32(&sB[s][ldrow * 40]) + (uint32_t)ldcol;
        const char* a = gA + (size_t)c * 64;
        const char* b = gB + (size_t)c * 64;
        cp16(da, a);      cp16(da + 16, a + 16);
        cp16(db, b);      cp16(db + 16, b + 16);
        cp_commit();
    };

    float acc[4][4][4] = {};

    prefetch(0); prefetch(1);

    int g  = lid >> 3, r8 = lid & 7;
    int a_m = wm + (g & 1) * 8 + r8;
    int a_k = (g >> 1) * 8;
    int b_n = wn + (g >> 1) * 8 + r8;
    int b_k = (g & 1) * 8;

    for (int kt = 0; kt < NK; kt++) {
        int s = kt & 1;
        if (kt + 1 < NK) cp_wait<1>(); else cp_wait<0>();
        __syncthreads();

        uint32_t baseA = smem_u32(&sA[s][0]);
        uint32_t baseB = smem_u32(&sB[s][0]);
#pragma unroll
        for (int ks = 0; ks < 2; ks++) {
            uint32_t a[4][4], b[4][2];
#pragma unroll
            for (int mt = 0; mt < 4; mt++) {
                uint32_t addr = baseA + (uint32_t)(a_m + mt*16) * 80u
                                      + (uint32_t)(a_k + ks*16) * 2u;
                ldsm4(a[mt][0], a[mt][1], a[mt][2], a[mt][3], addr);
            }
#pragma unroll
            for (int nt = 0; nt < 2; nt++) {
                uint32_t r0, r1, r2, r3;
                uint32_t addr = baseB + (uint32_t)(b_n + nt*16) * 80u
                                      + (uint32_t)(b_k + ks*16) * 2u;
                ldsm4(r0, r1, r2, r3, addr);
                b[nt*2][0] = r0;   b[nt*2][1] = r1;
                b[nt*2+1][0] = r2; b[nt*2+1][1] = r3;
            }
#pragma unroll
            for (int mt = 0; mt < 4; mt++)
#pragma unroll
                for (int nn = 0; nn < 4; nn++)
                    mma16816(acc[mt][nn], a[mt], b[nn]);
        }
        __syncthreads();
        if (kt + 2 < NK) prefetch(kt + 2);
    }

    int row = lid >> 2, col = (lid & 3) * 2;
#pragma unroll
    for (int mt = 0; mt < 4; mt++) {
#pragma unroll
        for (int nn = 0; nn < 4; nn++) {
            int m = m0 + wm + mt*16 + row;
            int n = n0 + wn + nn*8 + col;
            float2 v0 = make_float2(acc[mt][nn][0], acc[mt][nn][1]);
            float2 v1 = make_float2(acc[mt][nn][2], acc[mt][nn][3]);
            if (RES) {
                float2 q0 = *(const float2*)(Rsd + (size_t)m * N + n);
                float2 q1 = *(const float2*)(Rsd + (size_t)(m+8) * N + n);
                v0.x += q0.x; v0.y += q0.y;
                v1.x += q1.x; v1.y += q1.y;
            }
            *(float2*)(C + (size_t)m * N + n)     = v0;
            *(float2*)(C + (size_t)(m+8) * N + n) = v1;
        }
    }
}

// ===========================================================================
// K3: RoPE + fp32->fp16 into head-major arrays. Q scaled by 0.125.
// ===========================================================================
__global__ void rope_split_kernel() {
    int idx = blockIdx.x * 256 + threadIdx.x;   // MROWS*3*16*32 total
    int d = idx & 31;
    int h = (idx >> 5) & 15;
    int ms = idx >> 9;            // m*3 + s
    int s = ms % 3;
    int m = ms / 3;
    int t = m & (SEQ - 1);
    int b = m >> 11;
    const float* src = g_qkv + (size_t)m * EDIM + s * DMODEL + h * HDIM;
    float f1 = src[d], f2 = src[d + 32];
    float y1, y2;
    if (s < 2) {
        float inv_freq = powf(10000.0f, -(float)d * (1.0f / 32.0f));
        float ang = (float)t * inv_freq;
        float sn, cs;
        sincosf(ang, &sn, &cs);
        y1 = f1 * cs - f2 * sn;
        y2 = f2 * cs + f1 * sn;
        if (s == 0) { y1 *= 0.125f; y2 *= 0.125f; }
    } else { y1 = f1; y2 = f2; }
    size_t base = (size_t)s * SEC_ELEMS + ((size_t)(b * NHEADS + h) * SEQ + t) * HDIM;
    g_split[base + d]      = __float2half_rn(y1);
    g_split[base + d + 32] = __float2half_rn(y2);
}

// ===========================================================================
// K4: HMMA causal flash attention, fp16 operands, fp32 softmax.
// grid (SEQ/64, NHEADS, BATCH), 128 threads (4 warps x 16 q-rows).
// Output fp16 into g_abf [MROWS, DMODEL].
// ===========================================================================
#define ATS 72                         // smem row stride in halfs
#define AT_TILE (64*ATS)               // one 64x64 array
#define ATT_SMEM ((1 + 4) * AT_TILE * 2)   // bytes = 46080

__global__ __launch_bounds__(128) void attn_mma_kernel() {
    extern __shared__ __half sh[];
    __half* Qh = sh;
    __half* KV = sh + AT_TILE;   // stage s: +s*2*AT_TILE; [Kh, Vh]

    int qt = blockIdx.x, hh = blockIdx.y, b = blockIdx.z;
    int bh = b * NHEADS + hh;
    int tid = threadIdx.x;
    int lid = tid & 31, wid = tid >> 5;
    int q0 = qt * 64;

    const __half* gq = g_split + 0*SEC_ELEMS + (size_t)bh * SEQ * HDIM;
    const __half* gk = g_split + 1*SEC_ELEMS + (size_t)bh * SEQ * HDIM;
    const __half* gv = g_split + 2*SEC_ELEMS + (size_t)bh * SEQ * HDIM;

    int ldrow = tid >> 1;          // 0..63
    int ldh   = (tid & 1) * 32;    // halfs offset within row

    // Q load (part of group 0)
    {
        const __half* s0 = gq + (size_t)(q0 + ldrow) * HDIM + ldh;
        uint32_t d0 = smem_u32(Qh + ldrow * ATS + ldh);
#pragma unroll
        for (int i = 0; i < 4; i++) cp16(d0 + i*16, s0 + i*8);
    }

    auto prefetch = [&](int kt) {
        int s = kt & 1;
        __half* base = KV + s * 2 * AT_TILE;
        size_t gr = (size_t)(kt * 64 + ldrow) * HDIM + ldh;
        const __half* srcs[2] = { gk + gr, gv + gr };
#pragma unroll
        for (int a = 0; a < 2; a++) {
            uint32_t dst = smem_u32(base + a * AT_TILE + ldrow * ATS + ldh);
#pragma unroll
            for (int i = 0; i < 4; i++) cp16(dst + i*16, srcs[a] + i*8);
        }
        cp_commit();
    };
    prefetch(0);   // group 0 = Q + tile 0

    float m0 = -1e30f, m1 = -1e30f, l0 = 0.f, l1 = 0.f;
    float oacc[8][4] = {};

    int g  = lid >> 3, r8 = lid & 7;
    int a_row = wid * 16 + (g & 1) * 8 + r8;   // Q smem row
    int a_kof = (g >> 1) * 8;                  // + kc*16
    int b_row = (g >> 1) * 8 + r8;             // K smem row within 16-pair (+p*16)
    int b_kof = (g & 1) * 8;
    int v_row = lid & 15;                      // + kc*16
    int v_col = (lid >> 4) * 8;                // + p*16
    int qrow_loc = wid * 16 + (lid >> 2);      // local q row for c0/c1

    for (int kt = 0; kt <= qt; kt++) {
        __syncthreads();
        if (kt < qt) { prefetch(kt + 1); cp_wait<1>(); } else { cp_wait<0>(); }
        __syncthreads();

        uint32_t bKh = smem_u32(KV + (kt & 1) * 2 * AT_TILE);
        uint32_t bVh = bKh + AT_TILE * 2;
        uint32_t bQh = smem_u32(Qh);

        // ---- S = Q K^T ----
        float sacc[8][4] = {};
#pragma unroll
        for (int kc = 0; kc < 4; kc++) {
            uint32_t ah[4];
            uint32_t aoff = (uint32_t)(a_row * ATS + kc*16 + a_kof) * 2u;
            ldsm4(ah[0], ah[1], ah[2], ah[3], bQh + aoff);
            uint32_t bhf[8][2];
#pragma unroll
            for (int p = 0; p < 4; p++) {
                uint32_t boff = (uint32_t)((p*16 + b_row) * ATS + kc*16 + b_kof) * 2u;
                uint32_t r0, r1, r2, r3;
                ldsm4(r0, r1, r2, r3, bKh + boff);
                bhf[2*p][0] = r0; bhf[2*p][1] = r1;
                bhf[2*p+1][0] = r2; bhf[2*p+1][1] = r3;
            }
#pragma unroll
            for (int j = 0; j < 8; j++)
                mma16816(sacc[j], ah, bhf[j]);
        }

        // ---- causal mask on diagonal tile ----
        if (kt == qt) {
#pragma unroll
            for (int j = 0; j < 8; j++) {
                int col = j*8 + (lid & 3) * 2;
                if (col     > qrow_loc)     sacc[j][0] = -1e30f;
                if (col + 1 > qrow_loc)     sacc[j][1] = -1e30f;
                if (col     > qrow_loc + 8) sacc[j][2] = -1e30f;
                if (col + 1 > qrow_loc + 8) sacc[j][3] = -1e30f;
            }
        }

        // ---- online softmax (rows qrow_loc and +8) ----
        float mx0 = -1e30f, mx1 = -1e30f;
#pragma unroll
        for (int j = 0; j < 8; j++) {
            mx0 = fmaxf(mx0, fmaxf(sacc[j][0], sacc[j][1]));
            mx1 = fmaxf(mx1, fmaxf(sacc[j][2], sacc[j][3]));
        }
        mx0 = fmaxf(mx0, __shfl_xor_sync(0xffffffffu, mx0, 1));
        mx0 = fmaxf(mx0, __shfl_xor_sync(0xffffffffu, mx0, 2));
        mx1 = fmaxf(mx1, __shfl_xor_sync(0xffffffffu, mx1, 1));
        mx1 = fmaxf(mx1, __shfl_xor_sync(0xffffffffu, mx1, 2));
        float mn0 = fmaxf(m0, mx0), mn1 = fmaxf(m1, mx1);
        float al0 = __expf(m0 - mn0), al1 = __expf(m1 - mn1);
        float s0 = 0.f, s1 = 0.f;
#pragma unroll
        for (int j = 0; j < 8; j++) {
            sacc[j][0] = __expf(sacc[j][0] - mn0);
            sacc[j][1] = __expf(sacc[j][1] - mn0);
            sacc[j][2] = __expf(sacc[j][2] - mn1);
            sacc[j][3] = __expf(sacc[j][3] - mn1);
            s0 += sacc[j][0] + sacc[j][1];
            s1 += sacc[j][2] + sacc[j][3];
        }
        s0 += __shfl_xor_sync(0xffffffffu, s0, 1);
        s0 += __shfl_xor_sync(0xffffffffu, s0, 2);
        s1 += __shfl_xor_sync(0xffffffffu, s1, 1);
        s1 += __shfl_xor_sync(0xffffffffu, s1, 2);
        l0 = l0 * al0 + s0;  l1 = l1 * al1 + s1;
        m0 = mn0;  m1 = mn1;
#pragma unroll
        for (int j = 0; j < 8; j++) {
            oacc[j][0] *= al0; oacc[j][1] *= al0;
            oacc[j][2] *= al1; oacc[j][3] *= al1;
        }

        // ---- P fragments (fp16) ----
        uint32_t ph01[8], ph23[8];
#pragma unroll
        for (int j = 0; j < 8; j++) {
            __half2 t0 = __floats2half2_rn(sacc[j][0], sacc[j][1]);
            __half2 t1 = __floats2half2_rn(sacc[j][2], sacc[j][3]);
            ph01[j] = *(uint32_t*)&t0;
            ph23[j] = *(uint32_t*)&t1;
        }

        // ---- O += P V, V via ldmatrix.trans ----
#pragma unroll
        for (int kc = 0; kc < 4; kc++) {
            uint32_t aH[4] = { ph01[2*kc], ph23[2*kc], ph01[2*kc+1], ph23[2*kc+1] };
#pragma unroll
            for (int p = 0; p < 4; p++) {
                uint32_t voff = (uint32_t)((kc*16 + v_row) * ATS + p*16 + v_col) * 2u;
                uint32_t h0, h1, h2, h3;
                ldsm4t(h0, h1, h2, h3, bVh + voff);
                uint32_t bv0[2] = { h0, h1 }, bv1[2] = { h2, h3 };
                mma16816(oacc[2*p],   aH, bv0);
                mma16816(oacc[2*p+1], aH, bv1);
            }
        }
    }

    // ---- epilogue: normalize, write fp16 into g_abf ----
    float inv0 = 1.0f / l0, inv1 = 1.0f / l1;
    int mg0 = b * SEQ + q0 + qrow_loc;
    int mg1 = mg0 + 8;
#pragma unroll
    for (int j = 0; j < 8; j++) {
        int col = hh * HDIM + j*8 + (lid & 3) * 2;
        __half2 hp0 = __floats2half2_rn(oacc[j][0] * inv0, oacc[j][1] * inv0);
        __half2 hp1 = __floats2half2_rn(oacc[j][2] * inv1, oacc[j][3] * inv1);
        *(__half2*)(g_abf + (size_t)mg0 * KD + col) = hp0;
        *(__half2*)(g_abf + (size_t)mg1 * KD + col) = hp1;
    }
}

// ===========================================================================
extern "C" void kernel_launch(void* const* d_in, const int* in_sizes, int n_in,
                              void* d_out, int out_size) {
    const float* x      = (const float*)d_in[0];
    const float* norm_w = (const float*)d_in[1];
    const float* w_qkv  = (const float*)d_in[2];
    const float* w_out  = (const float*)d_in[3];
    float* out = (float*)d_out;

    __half *p_abf, *p_bbf, *p_bbf2;
    float *p_qkv;
    cudaGetSymbolAddress((void**)&p_abf,  g_abf);
    cudaGetSymbolAddress((void**)&p_bbf,  g_bbf);
    cudaGetSymbolAddress((void**)&p_bbf2, g_bbf2);
    cudaGetSymbolAddress((void**)&p_qkv,  g_qkv);

    cudaFuncSetAttribute(attn_mma_kernel,
                         cudaFuncAttributeMaxDynamicSharedMemorySize, ATT_SMEM);

    // 1. RMSNorm -> fp16
    rmsnorm_kernel<<<MROWS, 256>>>(x, norm_w);

    // 2. w_qkv -> fp16
    convert_w_kernel<<<(EDIM*DMODEL)/256, 256>>>(w_qkv, p_bbf, EDIM*DMODEL);

    // 3. QKV projection (HMMA fp16, K=1024)
    gemm_mma_kernel<false><<<dim3(EDIM/128, MROWS/128), 256>>>(
        p_abf, p_bbf, nullptr, p_qkv, EDIM);

    // 4. RoPE + fp16 head-major
    rope_split_kernel<<<(MROWS * 3 * NHEADS * 32) / 256, 256>>>();

    // 5. HMMA causal flash attention
    attn_mma_kernel<<<dim3(SEQ/64, NHEADS, BATCH), 128, ATT_SMEM>>>();

    // 6. w_out -> fp16
    convert_w_kernel<<<(DMODEL*DMODEL)/256, 256>>>(w_out, p_bbf2, DMODEL*DMODEL);

    // 7. Output projection + residual (HMMA fp16)
    gemm_mma_kernel<true><<<dim3(DMODEL/128, MROWS/128), 256>>>(
        p_abf, p_bbf2, x, out, DMODEL);
}

// round 8
// speedup vs baseline: 2.8397x; 1.0439x over previous
#include <cuda_runtime.h>
#include <cuda_fp16.h>
#include <math.h>
#include <stdint.h>

#define BATCH   2
#define SEQ     2048
#define DMODEL  1024
#define NHEADS  16
#define HDIM    64
#define MROWS   (BATCH*SEQ)        // 4096
#define EDIM    (3*DMODEL)         // 3072
#define KD      DMODEL             // GEMM K = 1024
#define NK      (KD/32)            // 32 k-chunks of 32
#define BH      (BATCH*NHEADS)     // 32

// Scratch (device globals; no runtime allocation allowed)
__device__ __align__(128) __half g_abf[MROWS*KD];      // fp16 activations (h, then attn-out)
__device__ __align__(128) __half g_bbf[EDIM*KD];       // fp16 w_qkv
__device__ __align__(128) __half g_bbf2[DMODEL*KD];    // fp16 w_out
// head-major fp16 q/k/v: [sec: q, k, v][bh][t][d]
__device__ __align__(128) __half g_split[(size_t)3*BH*SEQ*HDIM];
#define SEC_ELEMS ((size_t)BH*SEQ*HDIM)

// ===========================================================================
// helpers
// ===========================================================================
__device__ __forceinline__ uint32_t smem_u32(const void* p) {
    uint32_t a;
    asm("{ .reg .u64 t; cvta.to.shared.u64 t, %1; cvt.u32.u64 %0, t; }" : "=r"(a) : "l"(p));
    return a;
}
__device__ __forceinline__ void cp16(uint32_t smem, const void* g) {
    asm volatile("cp.async.cg.shared.global [%0], [%1], 16;" :: "r"(smem), "l"(g) : "memory");
}
__device__ __forceinline__ void cp_commit() {
    asm volatile("cp.async.commit_group;" ::: "memory");
}
template<int N> __device__ __forceinline__ void cp_wait() {
    asm volatile("cp.async.wait_group %0;" :: "n"(N) : "memory");
}
__device__ __forceinline__ void ldsm4(uint32_t& r0, uint32_t& r1, uint32_t& r2, uint32_t& r3,
                                      uint32_t addr) {
    asm volatile("ldmatrix.sync.aligned.m8n8.x4.shared.b16 {%0,%1,%2,%3}, [%4];"
                 : "=r"(r0), "=r"(r1), "=r"(r2), "=r"(r3) : "r"(addr));
}
__device__ __forceinline__ void ldsm4t(uint32_t& r0, uint32_t& r1, uint32_t& r2, uint32_t& r3,
                                       uint32_t addr) {
    asm volatile("ldmatrix.sync.aligned.m8n8.x4.trans.shared.b16 {%0,%1,%2,%3}, [%4];"
                 : "=r"(r0), "=r"(r1), "=r"(r2), "=r"(r3) : "r"(addr));
}
__device__ __forceinline__ void mma16816(float* d, const uint32_t* a, const uint32_t* b) {
    asm volatile("mma.sync.aligned.m16n8k16.row.col.f32.f16.f16.f32 "
                 "{%0,%1,%2,%3}, {%4,%5,%6,%7}, {%8,%9}, {%0,%1,%2,%3};"
                 : "+f"(d[0]), "+f"(d[1]), "+f"(d[2]), "+f"(d[3])
                 : "r"(a[0]), "r"(a[1]), "r"(a[2]), "r"(a[3]), "r"(b[0]), "r"(b[1]));
}

// ===========================================================================
// K1: RMSNorm -> fp16. One block per row, 256 threads.
// ===========================================================================
__global__ void rmsnorm_kernel(const float* __restrict__ x, const float* __restrict__ w) {
    int row = blockIdx.x;
    int tid = threadIdx.x;
    const float* xr = x + (size_t)row * DMODEL;
    float v[4];
    float ss = 0.f;
#pragma unroll
    for (int i = 0; i < 4; i++) { v[i] = xr[tid + i*256]; ss += v[i]*v[i]; }
    __shared__ float red[256];
    red[tid] = ss;
    __syncthreads();
#pragma unroll
    for (int off = 128; off > 0; off >>= 1) {
        if (tid < off) red[tid] += red[tid + off];
        __syncthreads();
    }
    float inv = rsqrtf(red[0] * (1.0f / DMODEL) + 1e-6f);
    __half* d = g_abf + (size_t)row * KD;
#pragma unroll
    for (int i = 0; i < 4; i++) {
        int col = tid + i*256;
        d[col] = __float2half_rn(v[i] * inv * w[col]);
    }
}

// ===========================================================================
// Weight conversion: both weights in one launch.
// ===========================================================================
__global__ void convert_w_kernel(const float* __restrict__ w_qkv,
                                 const float* __restrict__ w_out) {
    int idx = blockIdx.x * 256 + threadIdx.x;   // 4M total
    if (idx < EDIM*DMODEL) {
        g_bbf[idx] = __float2half_rn(w_qkv[idx]);
    } else {
        int j = idx - EDIM*DMODEL;
        g_bbf2[j] = __float2half_rn(w_out[j]);
    }
}

// ===========================================================================
// HMMA GEMM (fp16, K=1024). QKV=true: epilogue writes fp16 head-major into
// g_split. QKV=false: float C + residual.
// 128x128x32 CTA tile, 256 thr (8 warps 2x4), warp tile 64x32, 2-stage.
// ===========================================================================
template<bool QKV>
__global__ __launch_bounds__(256) void gemm_mma_kernel(
    const __half* __restrict__ A, const __half* __restrict__ Bw,
    const float* __restrict__ Rsd, float* __restrict__ C, int N)
{
    __shared__ __align__(128) __half sA[2][128*40];
    __shared__ __align__(128) __half sB[2][128*40];

    int tid = threadIdx.x, lid = tid & 31, wid = tid >> 5;
    int wm = (wid & 1) * 64;
    int wn = (wid >> 1) * 32;
    int m0 = blockIdx.y * 128, n0 = blockIdx.x * 128;

    int ldrow = tid >> 1;
    int ldcol = (tid & 1) * 32;       // bytes
    const char* gA = (const char*)(A  + (size_t)(m0 + ldrow) * KD) + ldcol;
    const char* gB = (const char*)(Bw + (size_t)(n0 + ldrow) * KD) + ldcol;

    auto prefetch = [&](int c) {
        int s = c & 1;
        uint32_t da = smem_u32(&sA[s][ldrow * 40]) + (uint32_t)ldcol;
        uint32_t db = smem_u32(&sB[s][ldrow * 40]) + (uint32_t)ldcol;
        const char* a = gA + (size_t)c * 64;
        const char* b = gB + (size_t)c * 64;
        cp16(da, a);      cp16(da + 16, a + 16);
        cp16(db, b);      cp16(db + 16, b + 16);
        cp_commit();
    };

    float acc[4][4][4] = {};

    prefetch(0); prefetch(1);

    int g  = lid >> 3, r8 = lid & 7;
    int a_m = wm + (g & 1) * 8 + r8;
    int a_k = (g >> 1) * 8;
    int b_n = wn + (g >> 1) * 8 + r8;
    int b_k = (g & 1) * 8;

    for (int kt = 0; kt < NK; kt++) {
        int s = kt & 1;
        if (kt + 1 < NK) cp_wait<1>(); else cp_wait<0>();
        __syncthreads();

        uint32_t baseA = smem_u32(&sA[s][0]);
        uint32_t baseB = smem_u32(&sB[s][0]);
#pragma unroll
        for (int ks = 0; ks < 2; ks++) {
            uint32_t a[4][4], b[4][2];
#pragma unroll
            for (int mt = 0; mt < 4; mt++) {
                uint32_t addr = baseA + (uint32_t)(a_m + mt*16) * 80u
                                      + (uint32_t)(a_k + ks*16) * 2u;
                ldsm4(a[mt][0], a[mt][1], a[mt][2], a[mt][3], addr);
            }
#pragma unroll
            for (int nt = 0; nt < 2; nt++) {
                uint32_t r0, r1, r2, r3;
                uint32_t addr = baseB + (uint32_t)(b_n + nt*16) * 80u
                                      + (uint32_t)(b_k + ks*16) * 2u;
                ldsm4(r0, r1, r2, r3, addr);
                b[nt*2][0] = r0;   b[nt*2][1] = r1;
                b[nt*2+1][0] = r2; b[nt*2+1][1] = r3;
            }
#pragma unroll
            for (int mt = 0; mt < 4; mt++)
#pragma unroll
                for (int nn = 0; nn < 4; nn++)
                    mma16816(acc[mt][nn], a[mt], b[nn]);
        }
        __syncthreads();
        if (kt + 2 < NK) prefetch(kt + 2);
    }

    int row = lid >> 2, col = (lid & 3) * 2;
#pragma unroll
    for (int mt = 0; mt < 4; mt++) {
#pragma unroll
        for (int nn = 0; nn < 4; nn++) {
            int m = m0 + wm + mt*16 + row;
            int n = n0 + wn + nn*8 + col;
            if (QKV) {
                // n -> (sec, head, d);  m -> (batch, t).  Write head-major fp16.
                int sc = n >> 10, h = (n >> 6) & 15, d = n & 63;
                int t = m & (SEQ - 1), bb = m >> 11;
                size_t base = (size_t)sc * SEC_ELEMS
                            + ((size_t)(bb * NHEADS + h) * SEQ + t) * HDIM + d;
                __half2 v0 = __floats2half2_rn(acc[mt][nn][0], acc[mt][nn][1]);
                __half2 v1 = __floats2half2_rn(acc[mt][nn][2], acc[mt][nn][3]);
                *(__half2*)(g_split + base)            = v0;   // row t
                *(__half2*)(g_split + base + 8*HDIM)   = v1;   // row t+8 (same batch)
            } else {
                float2 v0 = make_float2(acc[mt][nn][0], acc[mt][nn][1]);
                float2 v1 = make_float2(acc[mt][nn][2], acc[mt][nn][3]);
                float2 q0 = *(const float2*)(Rsd + (size_t)m * N + n);
                float2 q1 = *(const float2*)(Rsd + (size_t)(m+8) * N + n);
                v0.x += q0.x; v0.y += q0.y;
                v1.x += q1.x; v1.y += q1.y;
                *(float2*)(C + (size_t)m * N + n)     = v0;
                *(float2*)(C + (size_t)(m+8) * N + n) = v1;
            }
        }
    }
}

// ===========================================================================
// K3: in-place fp16 RoPE on Q,K sections of g_split. Q scaled by 0.125.
// One thread per (bh, sec, t, dpair): rotates (2k, 2k+1) with (.., +32).
// ===========================================================================
__global__ void rope_kernel() {
    int idx = blockIdx.x * 256 + threadIdx.x;   // BH*2*SEQ*16 = 2,097,152
    int k  = idx & 15;
    int t  = (idx >> 4) & (SEQ - 1);
    int sc = (idx >> 15) & 1;                   // 0 = q, 1 = k
    int bh = idx >> 16;
    __half* p = g_split + (size_t)sc * SEC_ELEMS + ((size_t)bh * SEQ + t) * HDIM + 2*k;
    float2 a = __half22float2(*(__half2*)(p));
    float2 b = __half22float2(*(__half2*)(p + 32));
    float if0 = powf(10000.0f, -(float)(2*k)   * (1.0f/32.0f));
    float if1 = powf(10000.0f, -(float)(2*k+1) * (1.0f/32.0f));
    float s0, c0, s1, c1;
    sincosf((float)t * if0, &s0, &c0);
    sincosf((float)t * if1, &s1, &c1);
    float y0 = a.x*c0 - b.x*s0, y1 = a.y*c1 - b.y*s1;
    float z0 = b.x*c0 + a.x*s0, z1 = b.y*c1 + a.y*s1;
    if (sc == 0) { y0 *= 0.125f; y1 *= 0.125f; z0 *= 0.125f; z1 *= 0.125f; }
    *(__half2*)(p)      = __floats2half2_rn(y0, y1);
    *(__half2*)(p + 32) = __floats2half2_rn(z0, z1);
}

// ===========================================================================
// K4: HMMA causal flash attention, fp16 operands, fp32 softmax.
// grid (SEQ/64, NHEADS, BATCH), 128 threads (4 warps x 16 q-rows).
// Output fp16 into g_abf [MROWS, DMODEL].
// ===========================================================================
#define ATS 72                         // smem row stride in halfs
#define AT_TILE (64*ATS)               // one 64x64 array
#define ATT_SMEM ((1 + 4) * AT_TILE * 2)   // bytes = 46080

__global__ __launch_bounds__(128) void attn_mma_kernel() {
    extern __shared__ __half sh[];
    __half* Qh = sh;
    __half* KV = sh + AT_TILE;   // stage s: +s*2*AT_TILE; [Kh, Vh]

    int qt = blockIdx.x, hh = blockIdx.y, b = blockIdx.z;
    int bh = b * NHEADS + hh;
    int tid = threadIdx.x;
    int lid = tid & 31, wid = tid >> 5;
    int q0 = qt * 64;

    const __half* gq = g_split + 0*SEC_ELEMS + (size_t)bh * SEQ * HDIM;
    const __half* gk = g_split + 1*SEC_ELEMS + (size_t)bh * SEQ * HDIM;
    const __half* gv = g_split + 2*SEC_ELEMS + (size_t)bh * SEQ * HDIM;

    int ldrow = tid >> 1;          // 0..63
    int ldh   = (tid & 1) * 32;    // halfs offset within row

    // Q load (part of group 0)
    {
        const __half* s0 = gq + (size_t)(q0 + ldrow) * HDIM + ldh;
        uint32_t d0 = smem_u32(Qh + ldrow * ATS + ldh);
#pragma unroll
        for (int i = 0; i < 4; i++) cp16(d0 + i*16, s0 + i*8);
    }

    auto prefetch = [&](int kt) {
        int s = kt & 1;
        __half* base = KV + s * 2 * AT_TILE;
        size_t gr = (size_t)(kt * 64 + ldrow) * HDIM + ldh;
        const __half* srcs[2] = { gk + gr, gv + gr };
#pragma unroll
        for (int a = 0; a < 2; a++) {
            uint32_t dst = smem_u32(base + a * AT_TILE + ldrow * ATS + ldh);
#pragma unroll
            for (int i = 0; i < 4; i++) cp16(dst + i*16, srcs[a] + i*8);
        }
        cp_commit();
    };
    prefetch(0);   // group 0 = Q + tile 0

    float m0 = -1e30f, m1 = -1e30f, l0 = 0.f, l1 = 0.f;
    float oacc[8][4] = {};

    int g  = lid >> 3, r8 = lid & 7;
    int a_row = wid * 16 + (g & 1) * 8 + r8;   // Q smem row
    int a_kof = (g >> 1) * 8;                  // + kc*16
    int b_row = (g >> 1) * 8 + r8;             // K smem row within 16-pair (+p*16)
    int b_kof = (g & 1) * 8;
    int v_row = lid & 15;                      // + kc*16
    int v_col = (lid >> 4) * 8;                // + p*16
    int qrow_loc = wid * 16 + (lid >> 2);      // local q row for c0/c1

    for (int kt = 0; kt <= qt; kt++) {
        __syncthreads();
        if (kt < qt) { prefetch(kt + 1); cp_wait<1>(); } else { cp_wait<0>(); }
        __syncthreads();

        uint32_t bKh = smem_u32(KV + (kt & 1) * 2 * AT_TILE);
        uint32_t bVh = bKh + AT_TILE * 2;
        uint32_t bQh = smem_u32(Qh);

        // ---- S = Q K^T ----
        float sacc[8][4] = {};
#pragma unroll
        for (int kc = 0; kc < 4; kc++) {
            uint32_t ah[4];
            uint32_t aoff = (uint32_t)(a_row * ATS + kc*16 + a_kof) * 2u;
            ldsm4(ah[0], ah[1], ah[2], ah[3], bQh + aoff);
            uint32_t bhf[8][2];
#pragma unroll
            for (int p = 0; p < 4; p++) {
                uint32_t boff = (uint32_t)((p*16 + b_row) * ATS + kc*16 + b_kof) * 2u;
                uint32_t r0, r1, r2, r3;
                ldsm4(r0, r1, r2, r3, bKh + boff);
                bhf[2*p][0] = r0; bhf[2*p][1] = r1;
                bhf[2*p+1][0] = r2; bhf[2*p+1][1] = r3;
            }
#pragma unroll
            for (int j = 0; j < 8; j++)
                mma16816(sacc[j], ah, bhf[j]);
        }

        // ---- causal mask on diagonal tile ----
        if (kt == qt) {
#pragma unroll
            for (int j = 0; j < 8; j++) {
                int col = j*8 + (lid & 3) * 2;
                if (col     > qrow_loc)     sacc[j][0] = -1e30f;
                if (col + 1 > qrow_loc)     sacc[j][1] = -1e30f;
                if (col     > qrow_loc + 8) sacc[j][2] = -1e30f;
                if (col + 1 > qrow_loc + 8) sacc[j][3] = -1e30f;
            }
        }

        // ---- online softmax (rows qrow_loc and +8) ----
        float mx0 = -1e30f, mx1 = -1e30f;
#pragma unroll
        for (int j = 0; j < 8; j++) {
            mx0 = fmaxf(mx0, fmaxf(sacc[j][0], sacc[j][1]));
            mx1 = fmaxf(mx1, fmaxf(sacc[j][2], sacc[j][3]));
        }
        mx0 = fmaxf(mx0, __shfl_xor_sync(0xffffffffu, mx0, 1));
        mx0 = fmaxf(mx0, __shfl_xor_sync(0xffffffffu, mx0, 2));
        mx1 = fmaxf(mx1, __shfl_xor_sync(0xffffffffu, mx1, 1));
        mx1 = fmaxf(mx1, __shfl_xor_sync(0xffffffffu, mx1, 2));
        float mn0 = fmaxf(m0, mx0), mn1 = fmaxf(m1, mx1);
        float al0 = __expf(m0 - mn0), al1 = __expf(m1 - mn1);
        float s0 = 0.f, s1 = 0.f;
#pragma unroll
        for (int j = 0; j < 8; j++) {
            sacc[j][0] = __expf(sacc[j][0] - mn0);
            sacc[j][1] = __expf(sacc[j][1] - mn0);
            sacc[j][2] = __expf(sacc[j][2] - mn1);
            sacc[j][3] = __expf(sacc[j][3] - mn1);
            s0 += sacc[j][0] + sacc[j][1];
            s1 += sacc[j][2] + sacc[j][3];
        }
        s0 += __shfl_xor_sync(0xffffffffu, s0, 1);
        s0 += __shfl_xor_sync(0xffffffffu, s0, 2);
        s1 += __shfl_xor_sync(0xffffffffu, s1, 1);
        s1 += __shfl_xor_sync(0xffffffffu, s1, 2);
        l0 = l0 * al0 + s0;  l1 = l1 * al1 + s1;
        m0 = mn0;  m1 = mn1;
#pragma unroll
        for (int j = 0; j < 8; j++) {
            oacc[j][0] *= al0; oacc[j][1] *= al0;
            oacc[j][2] *= al1; oacc[j][3] *= al1;
        }

        // ---- P fragments (fp16) ----
        uint32_t ph01[8], ph23[8];
#pragma unroll
        for (int j = 0; j < 8; j++) {
            __half2 t0 = __floats2half2_rn(sacc[j][0], sacc[j][1]);
            __half2 t1 = __floats2half2_rn(sacc[j][2], sacc[j][3]);
            ph01[j] = *(uint32_t*)&t0;
            ph23[j] = *(uint32_t*)&t1;
        }

        // ---- O += P V, V via ldmatrix.trans ----
#pragma unroll
        for (int kc = 0; kc < 4; kc++) {
            uint32_t aH[4] = { ph01[2*kc], ph23[2*kc], ph01[2*kc+1], ph23[2*kc+1] };
#pragma unroll
            for (int p = 0; p < 4; p++) {
                uint32_t voff = (uint32_t)((kc*16 + v_row) * ATS + p*16 + v_col) * 2u;
                uint32_t h0, h1, h2, h3;
                ldsm4t(h0, h1, h2, h3, bVh + voff);
                uint32_t bv0[2] = { h0, h1 }, bv1[2] = { h2, h3 };
                mma16816(oacc[2*p],   aH, bv0);
                mma16816(oacc[2*p+1], aH, bv1);
            }
        }
    }

    // ---- epilogue: normalize, write fp16 into g_abf ----
    float inv0 = 1.0f / l0, inv1 = 1.0f / l1;
    int mg0 = b * SEQ + q0 + qrow_loc;
    int mg1 = mg0 + 8;
#pragma unroll
    for (int j = 0; j < 8; j++) {
        int col = hh * HDIM + j*8 + (lid & 3) * 2;
        __half2 hp0 = __floats2half2_rn(oacc[j][0] * inv0, oacc[j][1] * inv0);
        __half2 hp1 = __floats2half2_rn(oacc[j][2] * inv1, oacc[j][3] * inv1);
        *(__half2*)(g_abf + (size_t)mg0 * KD + col) = hp0;
        *(__half2*)(g_abf + (size_t)mg1 * KD + col) = hp1;
    }
}

// ===========================================================================
extern "C" void kernel_launch(void* const* d_in, const int* in_sizes, int n_in,
                              void* d_out, int out_size) {
    const float* x      = (const float*)d_in[0];
    const float* norm_w = (const float*)d_in[1];
    const float* w_qkv  = (const float*)d_in[2];
    const float* w_out  = (const float*)d_in[3];
    float* out = (float*)d_out;

    __half *p_abf, *p_bbf, *p_bbf2;
    cudaGetSymbolAddress((void**)&p_abf,  g_abf);
    cudaGetSymbolAddress((void**)&p_bbf,  g_bbf);
    cudaGetSymbolAddress((void**)&p_bbf2, g_bbf2);

    cudaFuncSetAttribute(attn_mma_kernel,
                         cudaFuncAttributeMaxDynamicSharedMemorySize, ATT_SMEM);

    // 1. RMSNorm -> fp16
    rmsnorm_kernel<<<MROWS, 256>>>(x, norm_w);

    // 2. both weights -> fp16 (one launch)
    convert_w_kernel<<<((EDIM+DMODEL)*DMODEL)/256, 256>>>(w_qkv, w_out);

    // 3. QKV projection (HMMA fp16); epilogue writes head-major fp16 g_split
    gemm_mma_kernel<true><<<dim3(EDIM/128, MROWS/128), 256>>>(
        p_abf, p_bbf, nullptr, nullptr, EDIM);

    // 4. RoPE in place on Q,K (fp16)
    rope_kernel<<<(BH * 2 * SEQ * 16) / 256, 256>>>();

    // 5. HMMA causal flash attention
    attn_mma_kernel<<<dim3(SEQ/64, NHEADS, BATCH), 128, ATT_SMEM>>>();

    // 6. Output projection + residual (HMMA fp16)
    gemm_mma_kernel<false><<<dim3(DMODEL/128, MROWS/128), 256>>>(
        p_abf, p_bbf2, x, out, DMODEL);
}

// round 9
// speedup vs baseline: 2.9187x; 1.0278x over previous
#include <cuda_runtime.h>
#include <cuda_fp16.h>
#include <math.h>
#include <stdint.h>

#define BATCH   2
#define SEQ     2048
#define DMODEL  1024
#define NHEADS  16
#define HDIM    64
#define MROWS   (BATCH*SEQ)        // 4096
#define EDIM    (3*DMODEL)         // 3072
#define KD      DMODEL             // GEMM K = 1024
#define NK      (KD/32)            // 32 k-chunks of 32
#define BH      (BATCH*NHEADS)     // 32

// Scratch (device globals; no runtime allocation allowed)
__device__ __align__(128) __half g_abf[MROWS*KD];      // fp16 activations (h, then attn-out)
__device__ __align__(128) __half g_bbf[EDIM*KD];       // fp16 w_qkv
__device__ __align__(128) __half g_bbf2[DMODEL*KD];    // fp16 w_out
// head-major fp16 q/k/v: [sec: q, k, v][bh][t][d]
__device__ __align__(128) __half g_split[(size_t)3*BH*SEQ*HDIM];
#define SEC_ELEMS ((size_t)BH*SEQ*HDIM)

// ===========================================================================
// helpers
// ===========================================================================
__device__ __forceinline__ uint32_t smem_u32(const void* p) {
    uint32_t a;
    asm("{ .reg .u64 t; cvta.to.shared.u64 t, %1; cvt.u32.u64 %0, t; }" : "=r"(a) : "l"(p));
    return a;
}
__device__ __forceinline__ void cp16(uint32_t smem, const void* g) {
    asm volatile("cp.async.cg.shared.global [%0], [%1], 16;" :: "r"(smem), "l"(g) : "memory");
}
__device__ __forceinline__ void cp_commit() {
    asm volatile("cp.async.commit_group;" ::: "memory");
}
template<int N> __device__ __forceinline__ void cp_wait() {
    asm volatile("cp.async.wait_group %0;" :: "n"(N) : "memory");
}
__device__ __forceinline__ void ldsm4(uint32_t& r0, uint32_t& r1, uint32_t& r2, uint32_t& r3,
                                      uint32_t addr) {
    asm volatile("ldmatrix.sync.aligned.m8n8.x4.shared.b16 {%0,%1,%2,%3}, [%4];"
                 : "=r"(r0), "=r"(r1), "=r"(r2), "=r"(r3) : "r"(addr));
}
__device__ __forceinline__ void ldsm4t(uint32_t& r0, uint32_t& r1, uint32_t& r2, uint32_t& r3,
                                       uint32_t addr) {
    asm volatile("ldmatrix.sync.aligned.m8n8.x4.trans.shared.b16 {%0,%1,%2,%3}, [%4];"
                 : "=r"(r0), "=r"(r1), "=r"(r2), "=r"(r3) : "r"(addr));
}
__device__ __forceinline__ void mma16816(float* d, const uint32_t* a, const uint32_t* b) {
    asm volatile("mma.sync.aligned.m16n8k16.row.col.f32.f16.f16.f32 "
                 "{%0,%1,%2,%3}, {%4,%5,%6,%7}, {%8,%9}, {%0,%1,%2,%3};"
                 : "+f"(d[0]), "+f"(d[1]), "+f"(d[2]), "+f"(d[3])
                 : "r"(a[0]), "r"(a[1]), "r"(a[2]), "r"(a[3]), "r"(b[0]), "r"(b[1]));
}

// ===========================================================================
// K1: RMSNorm -> fp16. One block per row, 256 threads.
// ===========================================================================
__global__ void rmsnorm_kernel(const float* __restrict__ x, const float* __restrict__ w) {
    int row = blockIdx.x;
    int tid = threadIdx.x;
    const float* xr = x + (size_t)row * DMODEL;
    float v[4];
    float ss = 0.f;
#pragma unroll
    for (int i = 0; i < 4; i++) { v[i] = xr[tid + i*256]; ss += v[i]*v[i]; }
    __shared__ float red[256];
    red[tid] = ss;
    __syncthreads();
#pragma unroll
    for (int off = 128; off > 0; off >>= 1) {
        if (tid < off) red[tid] += red[tid + off];
        __syncthreads();
    }
    float inv = rsqrtf(red[0] * (1.0f / DMODEL) + 1e-6f);
    __half* d = g_abf + (size_t)row * KD;
#pragma unroll
    for (int i = 0; i < 4; i++) {
        int col = tid + i*256;
        d[col] = __float2half_rn(v[i] * inv * w[col]);
    }
}

// ===========================================================================
// Weight conversion: both weights in one launch.
// ===========================================================================
__global__ void convert_w_kernel(const float* __restrict__ w_qkv,
                                 const float* __restrict__ w_out) {
    int idx = blockIdx.x * 256 + threadIdx.x;   // 4M total
    if (idx < EDIM*DMODEL) {
        g_bbf[idx] = __float2half_rn(w_qkv[idx]);
    } else {
        int j = idx - EDIM*DMODEL;
        g_bbf2[j] = __float2half_rn(w_out[j]);
    }
}

// ===========================================================================
// HMMA GEMM (fp16, K=1024). QKV=true: epilogue writes fp16 head-major into
// g_split. QKV=false: float C + residual.
// ===========================================================================
template<bool QKV>
__global__ __launch_bounds__(256) void gemm_mma_kernel(
    const __half* __restrict__ A, const __half* __restrict__ Bw,
    const float* __restrict__ Rsd, float* __restrict__ C, int N)
{
    __shared__ __align__(128) __half sA[2][128*40];
    __shared__ __align__(128) __half sB[2][128*40];

    int tid = threadIdx.x, lid = tid & 31, wid = tid >> 5;
    int wm = (wid & 1) * 64;
    int wn = (wid >> 1) * 32;
    int m0 = blockIdx.y * 128, n0 = blockIdx.x * 128;

    int ldrow = tid >> 1;
    int ldcol = (tid & 1) * 32;       // bytes
    const char* gA = (const char*)(A  + (size_t)(m0 + ldrow) * KD) + ldcol;
    const char* gB = (const char*)(Bw + (size_t)(n0 + ldrow) * KD) + ldcol;

    auto prefetch = [&](int c) {
        int s = c & 1;
        uint32_t da = smem_u32(&sA[s][ldrow * 40]) + (uint32_t)ldcol;
        uint32_t db = smem_u32(&sB[s][ldrow * 40]) + (uint32_t)ldcol;
        const char* a = gA + (size_t)c * 64;
        const char* b = gB + (size_t)c * 64;
        cp16(da, a);      cp16(da + 16, a + 16);
        cp16(db, b);      cp16(db + 16, b + 16);
        cp_commit();
    };

    float acc[4][4][4] = {};

    prefetch(0); prefetch(1);

    int g  = lid >> 3, r8 = lid & 7;
    int a_m = wm + (g & 1) * 8 + r8;
    int a_k = (g >> 1) * 8;
    int b_n = wn + (g >> 1) * 8 + r8;
    int b_k = (g & 1) * 8;

    for (int kt = 0; kt < NK; kt++) {
        int s = kt & 1;
        if (kt + 1 < NK) cp_wait<1>(); else cp_wait<0>();
        __syncthreads();

        uint32_t baseA = smem_u32(&sA[s][0]);
        uint32_t baseB = smem_u32(&sB[s][0]);
#pragma unroll
        for (int ks = 0; ks < 2; ks++) {
            uint32_t a[4][4], b[4][2];
#pragma unroll
            for (int mt = 0; mt < 4; mt++) {
                uint32_t addr = baseA + (uint32_t)(a_m + mt*16) * 80u
                                      + (uint32_t)(a_k + ks*16) * 2u;
                ldsm4(a[mt][0], a[mt][1], a[mt][2], a[mt][3], addr);
            }
#pragma unroll
            for (int nt = 0; nt < 2; nt++) {
                uint32_t r0, r1, r2, r3;
                uint32_t addr = baseB + (uint32_t)(b_n + nt*16) * 80u
                                      + (uint32_t)(b_k + ks*16) * 2u;
                ldsm4(r0, r1, r2, r3, addr);
                b[nt*2][0] = r0;   b[nt*2][1] = r1;
                b[nt*2+1][0] = r2; b[nt*2+1][1] = r3;
            }
#pragma unroll
            for (int mt = 0; mt < 4; mt++)
#pragma unroll
                for (int nn = 0; nn < 4; nn++)
                    mma16816(acc[mt][nn], a[mt], b[nn]);
        }
        __syncthreads();
        if (kt + 2 < NK) prefetch(kt + 2);
    }

    int row = lid >> 2, col = (lid & 3) * 2;
#pragma unroll
    for (int mt = 0; mt < 4; mt++) {
#pragma unroll
        for (int nn = 0; nn < 4; nn++) {
            int m = m0 + wm + mt*16 + row;
            int n = n0 + wn + nn*8 + col;
            if (QKV) {
                int sc = n >> 10, h = (n >> 6) & 15, d = n & 63;
                int t = m & (SEQ - 1), bb = m >> 11;
                size_t base = (size_t)sc * SEC_ELEMS
                            + ((size_t)(bb * NHEADS + h) * SEQ + t) * HDIM + d;
                __half2 v0 = __floats2half2_rn(acc[mt][nn][0], acc[mt][nn][1]);
                __half2 v1 = __floats2half2_rn(acc[mt][nn][2], acc[mt][nn][3]);
                *(__half2*)(g_split + base)            = v0;
                *(__half2*)(g_split + base + 8*HDIM)   = v1;
            } else {
                float2 v0 = make_float2(acc[mt][nn][0], acc[mt][nn][1]);
                float2 v1 = make_float2(acc[mt][nn][2], acc[mt][nn][3]);
                float2 q0 = *(const float2*)(Rsd + (size_t)m * N + n);
                float2 q1 = *(const float2*)(Rsd + (size_t)(m+8) * N + n);
                v0.x += q0.x; v0.y += q0.y;
                v1.x += q1.x; v1.y += q1.y;
                *(float2*)(C + (size_t)m * N + n)     = v0;
                *(float2*)(C + (size_t)(m+8) * N + n) = v1;
            }
        }
    }
}

// ===========================================================================
// K3: in-place fp16 RoPE on Q,K sections of g_split.
// Q scaled by 0.125*log2(e) (exp2-domain softmax downstream).
// ===========================================================================
__global__ void rope_kernel() {
    int idx = blockIdx.x * 256 + threadIdx.x;   // BH*2*SEQ*16 = 2,097,152
    int k  = idx & 15;
    int t  = (idx >> 4) & (SEQ - 1);
    int sc = (idx >> 15) & 1;                   // 0 = q, 1 = k
    int bh = idx >> 16;
    __half* p = g_split + (size_t)sc * SEC_ELEMS + ((size_t)bh * SEQ + t) * HDIM + 2*k;
    float2 a = __half22float2(*(__half2*)(p));
    float2 b = __half22float2(*(__half2*)(p + 32));
    const float NEG_L2_10K_32 = -0.41524101186092029f;   // -log2(10000)/32
    float if0 = exp2f((float)(2*k)   * NEG_L2_10K_32);
    float if1 = exp2f((float)(2*k+1) * NEG_L2_10K_32);
    float s0, c0, s1, c1;
    sincosf((float)t * if0, &s0, &c0);
    sincosf((float)t * if1, &s1, &c1);
    float y0 = a.x*c0 - b.x*s0, y1 = a.y*c1 - b.y*s1;
    float z0 = b.x*c0 + a.x*s0, z1 = b.y*c1 + a.y*s1;
    if (sc == 0) {
        const float QS = 0.125f * 1.4426950408889634f;   // 1/sqrt(64) * log2(e)
        y0 *= QS; y1 *= QS; z0 *= QS; z1 *= QS;
    }
    *(__half2*)(p)      = __floats2half2_rn(y0, y1);
    *(__half2*)(p + 32) = __floats2half2_rn(z0, z1);
}

// ===========================================================================
// K4: HMMA causal flash attention, fp16 operands, exp2-domain fp32 softmax.
// grid (SEQ/64, NHEADS, BATCH), 128 threads (4 warps x 16 q-rows).
// Heavy-first: qt = gridDim.x-1-blockIdx.x. Q fragments hoisted.
// ===========================================================================
#define ATS 72                         // smem row stride in halfs
#define AT_TILE (64*ATS)               // one 64x64 array
#define ATT_SMEM ((1 + 4) * AT_TILE * 2)   // bytes = 46080

__global__ __launch_bounds__(128, 4) void attn_mma_kernel() {
    extern __shared__ __half sh[];
    __half* Qh = sh;
    __half* KV = sh + AT_TILE;   // stage s: +s*2*AT_TILE; [Kh, Vh]

    int qt = (gridDim.x - 1) - blockIdx.x;      // heavy CTAs first
    int hh = blockIdx.y, b = blockIdx.z;
    int bh = b * NHEADS + hh;
    int tid = threadIdx.x;
    int lid = tid & 31, wid = tid >> 5;
    int q0 = qt * 64;

    const __half* gq = g_split + 0*SEC_ELEMS + (size_t)bh * SEQ * HDIM;
    const __half* gk = g_split + 1*SEC_ELEMS + (size_t)bh * SEQ * HDIM;
    const __half* gv = g_split + 2*SEC_ELEMS + (size_t)bh * SEQ * HDIM;

    int ldrow = tid >> 1;          // 0..63
    int ldh   = (tid & 1) * 32;    // halfs offset within row

    // Q load (part of group 0)
    {
        const __half* s0 = gq + (size_t)(q0 + ldrow) * HDIM + ldh;
        uint32_t d0 = smem_u32(Qh + ldrow * ATS + ldh);
#pragma unroll
        for (int i = 0; i < 4; i++) cp16(d0 + i*16, s0 + i*8);
    }

    auto prefetch = [&](int kt) {
        int s = kt & 1;
        __half* base = KV + s * 2 * AT_TILE;
        size_t gr = (size_t)(kt * 64 + ldrow) * HDIM + ldh;
        const __half* srcs[2] = { gk + gr, gv + gr };
#pragma unroll
        for (int a = 0; a < 2; a++) {
            uint32_t dst = smem_u32(base + a * AT_TILE + ldrow * ATS + ldh);
#pragma unroll
            for (int i = 0; i < 4; i++) cp16(dst + i*16, srcs[a] + i*8);
        }
        cp_commit();
    };
    prefetch(0);                      // group 0 = Q + tile 0
    if (qt > 0) { prefetch(1); cp_wait<1>(); } else { cp_wait<0>(); }
    __syncthreads();

    int g  = lid >> 3, r8 = lid & 7;
    int a_row = wid * 16 + (g & 1) * 8 + r8;   // Q smem row
    int a_kof = (g >> 1) * 8;                  // + kc*16
    int b_row = (g >> 1) * 8 + r8;             // K smem row within 16-pair (+p*16)
    int b_kof = (g & 1) * 8;
    int v_row = lid & 15;                      // + kc*16
    int v_col = (lid >> 4) * 8;                // + p*16
    int qrow_loc = wid * 16 + (lid >> 2);      // local q row for c0/c1

    // ---- hoist Q fragments (loop-invariant) ----
    uint32_t aq[4][4];
    {
        uint32_t bQh = smem_u32(Qh);
#pragma unroll
        for (int kc = 0; kc < 4; kc++) {
            uint32_t aoff = (uint32_t)(a_row * ATS + kc*16 + a_kof) * 2u;
            ldsm4(aq[kc][0], aq[kc][1], aq[kc][2], aq[kc][3], bQh + aoff);
        }
    }

    float m0 = -1e30f, m1 = -1e30f, l0 = 0.f, l1 = 0.f;
    float oacc[8][4] = {};

    for (int kt = 0; kt <= qt; kt++) {
        uint32_t bKh = smem_u32(KV + (kt & 1) * 2 * AT_TILE);
        uint32_t bVh = bKh + AT_TILE * 2;

        // ---- S = Q K^T (exp2-domain: Q pre-scaled by 0.125*log2e) ----
        float sacc[8][4] = {};
#pragma unroll
        for (int kc = 0; kc < 4; kc++) {
            uint32_t bhf[8][2];
#pragma unroll
            for (int p = 0; p < 4; p++) {
                uint32_t boff = (uint32_t)((p*16 + b_row) * ATS + kc*16 + b_kof) * 2u;
                uint32_t r0, r1, r2, r3;
                ldsm4(r0, r1, r2, r3, bKh + boff);
                bhf[2*p][0] = r0; bhf[2*p][1] = r1;
                bhf[2*p+1][0] = r2; bhf[2*p+1][1] = r3;
            }
#pragma unroll
            for (int j = 0; j < 8; j++)
                mma16816(sacc[j], aq[kc], bhf[j]);
        }

        // ---- causal mask on diagonal tile ----
        if (kt == qt) {
#pragma unroll
            for (int j = 0; j < 8; j++) {
                int col = j*8 + (lid & 3) * 2;
                if (col     > qrow_loc)     sacc[j][0] = -1e30f;
                if (col + 1 > qrow_loc)     sacc[j][1] = -1e30f;
                if (col     > qrow_loc + 8) sacc[j][2] = -1e30f;
                if (col + 1 > qrow_loc + 8) sacc[j][3] = -1e30f;
            }
        }

        // ---- online softmax (exp2 domain), rows qrow_loc and +8 ----
        float mx0 = -1e30f, mx1 = -1e30f;
#pragma unroll
        for (int j = 0; j < 8; j++) {
            mx0 = fmaxf(mx0, fmaxf(sacc[j][0], sacc[j][1]));
            mx1 = fmaxf(mx1, fmaxf(sacc[j][2], sacc[j][3]));
        }
        mx0 = fmaxf(mx0, __shfl_xor_sync(0xffffffffu, mx0, 1));
        mx0 = fmaxf(mx0, __shfl_xor_sync(0xffffffffu, mx0, 2));
        mx1 = fmaxf(mx1, __shfl_xor_sync(0xffffffffu, mx1, 1));
        mx1 = fmaxf(mx1, __shfl_xor_sync(0xffffffffu, mx1, 2));
        float mn0 = fmaxf(m0, mx0), mn1 = fmaxf(m1, mx1);
        float al0 = exp2f(m0 - mn0), al1 = exp2f(m1 - mn1);
        float s0 = 0.f, s1 = 0.f;
#pragma unroll
        for (int j = 0; j < 8; j++) {
            sacc[j][0] = exp2f(sacc[j][0] - mn0);
            sacc[j][1] = exp2f(sacc[j][1] - mn0);
            sacc[j][2] = exp2f(sacc[j][2] - mn1);
            sacc[j][3] = exp2f(sacc[j][3] - mn1);
            s0 += sacc[j][0] + sacc[j][1];
            s1 += sacc[j][2] + sacc[j][3];
        }
        s0 += __shfl_xor_sync(0xffffffffu, s0, 1);
        s0 += __shfl_xor_sync(0xffffffffu, s0, 2);
        s1 += __shfl_xor_sync(0xffffffffu, s1, 1);
        s1 += __shfl_xor_sync(0xffffffffu, s1, 2);
        l0 = l0 * al0 + s0;  l1 = l1 * al1 + s1;
        m0 = mn0;  m1 = mn1;
#pragma unroll
        for (int j = 0; j < 8; j++) {
            oacc[j][0] *= al0; oacc[j][1] *= al0;
            oacc[j][2] *= al1; oacc[j][3] *= al1;
        }

        // ---- P fragments (fp16) ----
        uint32_t ph01[8], ph23[8];
#pragma unroll
        for (int j = 0; j < 8; j++) {
            __half2 t0 = __floats2half2_rn(sacc[j][0], sacc[j][1]);
            __half2 t1 = __floats2half2_rn(sacc[j][2], sacc[j][3]);
            ph01[j] = *(uint32_t*)&t0;
            ph23[j] = *(uint32_t*)&t1;
        }

        // ---- O += P V, V via ldmatrix.trans ----
#pragma unroll
        for (int kc = 0; kc < 4; kc++) {
            uint32_t aH[4] = { ph01[2*kc], ph23[2*kc], ph01[2*kc+1], ph23[2*kc+1] };
#pragma unroll
            for (int p = 0; p < 4; p++) {
                uint32_t voff = (uint32_t)((kc*16 + v_row) * ATS + p*16 + v_col) * 2u;
                uint32_t h0, h1, h2, h3;
                ldsm4t(h0, h1, h2, h3, bVh + voff);
                uint32_t bv0[2] = { h0, h1 }, bv1[2] = { h2, h3 };
                mma16816(oacc[2*p],   aH, bv0);
                mma16816(oacc[2*p+1], aH, bv1);
            }
        }

        // ---- advance pipeline ----
        if (kt < qt) {
            __syncthreads();
            if (kt + 2 <= qt) { prefetch(kt + 2); cp_wait<1>(); } else { cp_wait<0>(); }
            __syncthreads();
        }
    }

    // ---- epilogue: normalize, write fp16 into g_abf ----
    float inv0 = 1.0f / l0, inv1 = 1.0f / l1;
    int mg0 = b * SEQ + q0 + qrow_loc;
    int mg1 = mg0 + 8;
#pragma unroll
    for (int j = 0; j < 8; j++) {
        int col = hh * HDIM + j*8 + (lid & 3) * 2;
        __half2 hp0 = __floats2half2_rn(oacc[j][0] * inv0, oacc[j][1] * inv0);
        __half2 hp1 = __floats2half2_rn(oacc[j][2] * inv1, oacc[j][3] * inv1);
        *(__half2*)(g_abf + (size_t)mg0 * KD + col) = hp0;
        *(__half2*)(g_abf + (size_t)mg1 * KD + col) = hp1;
    }
}

// ===========================================================================
extern "C" void kernel_launch(void* const* d_in, const int* in_sizes, int n_in,
                              void* d_out, int out_size) {
    const float* x      = (const float*)d_in[0];
    const float* norm_w = (const float*)d_in[1];
    const float* w_qkv  = (const float*)d_in[2];
    const float* w_out  = (const float*)d_in[3];
    float* out = (float*)d_out;

    __half *p_abf, *p_bbf, *p_bbf2;
    cudaGetSymbolAddress((void**)&p_abf,  g_abf);
    cudaGetSymbolAddress((void**)&p_bbf,  g_bbf);
    cudaGetSymbolAddress((void**)&p_bbf2, g_bbf2);

    cudaFuncSetAttribute(attn_mma_kernel,
                         cudaFuncAttributeMaxDynamicSharedMemorySize, ATT_SMEM);

    // 1. RMSNorm -> fp16
    rmsnorm_kernel<<<MROWS, 256>>>(x, norm_w);

    // 2. both weights -> fp16 (one launch)
    convert_w_kernel<<<((EDIM+DMODEL)*DMODEL)/256, 256>>>(w_qkv, w_out);

    // 3. QKV projection (HMMA fp16); epilogue writes head-major fp16 g_split
    gemm_mma_kernel<true><<<dim3(EDIM/128, MROWS/128), 256>>>(
        p_abf, p_bbf, nullptr, nullptr, EDIM);

    // 4. RoPE in place on Q,K (fp16); Q scale folds in log2(e)
    rope_kernel<<<(BH * 2 * SEQ * 16) / 256, 256>>>();

    // 5. HMMA causal flash attention (heavy-first, exp2 softmax)
    attn_mma_kernel<<<dim3(SEQ/64, NHEADS, BATCH), 128, ATT_SMEM>>>();

    // 6. Output projection + residual (HMMA fp16)
    gemm_mma_kernel<false><<<dim3(DMODEL/128, MROWS/128), 256>>>(
        p_abf, p_bbf2, x, out, DMODEL);
}

// round 10
// speedup vs baseline: 3.0138x; 1.0326x over previous
#include <cuda_runtime.h>
#include <cuda_fp16.h>
#include <math.h>
#include <stdint.h>

#define BATCH   2
#define SEQ     2048
#define DMODEL  1024
#define NHEADS  16
#define HDIM    64
#define MROWS   (BATCH*SEQ)        // 4096
#define EDIM    (3*DMODEL)         // 3072
#define KD      DMODEL             // GEMM K = 1024
#define NK      (KD/32)            // 32 k-chunks of 32
#define BH      (BATCH*NHEADS)     // 32

// Scratch (device globals; no runtime allocation allowed)
__device__ __align__(128) __half g_abf[MROWS*KD];      // fp16 activations (h, then attn-out)
__device__ __align__(128) __half g_bbf[EDIM*KD];       // fp16 w_qkv
__device__ __align__(128) __half g_bbf2[DMODEL*KD];    // fp16 w_out
// head-major fp16 q/k/v: [sec: q, k, v][bh][t][d]
__device__ __align__(128) __half g_split[(size_t)3*BH*SEQ*HDIM];
#define SEC_ELEMS ((size_t)BH*SEQ*HDIM)

// ===========================================================================
// helpers
// ===========================================================================
__device__ __forceinline__ uint32_t smem_u32(const void* p) {
    uint32_t a;
    asm("{ .reg .u64 t; cvta.to.shared.u64 t, %1; cvt.u32.u64 %0, t; }" : "=r"(a) : "l"(p));
    return a;
}
__device__ __forceinline__ void cp16(uint32_t smem, const void* g) {
    asm volatile("cp.async.cg.shared.global [%0], [%1], 16;" :: "r"(smem), "l"(g) : "memory");
}
__device__ __forceinline__ void cp_commit() {
    asm volatile("cp.async.commit_group;" ::: "memory");
}
template<int N> __device__ __forceinline__ void cp_wait() {
    asm volatile("cp.async.wait_group %0;" :: "n"(N) : "memory");
}
__device__ __forceinline__ void ldsm4(uint32_t& r0, uint32_t& r1, uint32_t& r2, uint32_t& r3,
                                      uint32_t addr) {
    asm volatile("ldmatrix.sync.aligned.m8n8.x4.shared.b16 {%0,%1,%2,%3}, [%4];"
                 : "=r"(r0), "=r"(r1), "=r"(r2), "=r"(r3) : "r"(addr));
}
__device__ __forceinline__ void ldsm4t(uint32_t& r0, uint32_t& r1, uint32_t& r2, uint32_t& r3,
                                       uint32_t addr) {
    asm volatile("ldmatrix.sync.aligned.m8n8.x4.trans.shared.b16 {%0,%1,%2,%3}, [%4];"
                 : "=r"(r0), "=r"(r1), "=r"(r2), "=r"(r3) : "r"(addr));
}
__device__ __forceinline__ void mma16816(float* d, const uint32_t* a, const uint32_t* b) {
    asm volatile("mma.sync.aligned.m16n8k16.row.col.f32.f16.f16.f32 "
                 "{%0,%1,%2,%3}, {%4,%5,%6,%7}, {%8,%9}, {%0,%1,%2,%3};"
                 : "+f"(d[0]), "+f"(d[1]), "+f"(d[2]), "+f"(d[3])
                 : "r"(a[0]), "r"(a[1]), "r"(a[2]), "r"(a[3]), "r"(b[0]), "r"(b[1]));
}

// ===========================================================================
// K1: RMSNorm -> fp16. One block per row, 256 threads, float4 + warp reduce.
// ===========================================================================
__global__ void rmsnorm_kernel(const float* __restrict__ x, const float* __restrict__ w) {
    int row = blockIdx.x;
    int tid = threadIdx.x;
    float4 v = *(const float4*)(x + (size_t)row * DMODEL + tid * 4);
    float ss = v.x*v.x + v.y*v.y + v.z*v.z + v.w*v.w;
#pragma unroll
    for (int off = 16; off > 0; off >>= 1)
        ss += __shfl_xor_sync(0xffffffffu, ss, off);
    __shared__ float red[8];
    if ((tid & 31) == 0) red[tid >> 5] = ss;
    __syncthreads();
    float tot = red[0] + red[1] + red[2] + red[3]
              + red[4] + red[5] + red[6] + red[7];
    float inv = rsqrtf(tot * (1.0f / DMODEL) + 1e-6f);
    float4 wv = *(const float4*)(w + tid * 4);
    __half2 h0 = __floats2half2_rn(v.x * inv * wv.x, v.y * inv * wv.y);
    __half2 h1 = __floats2half2_rn(v.z * inv * wv.z, v.w * inv * wv.w);
    uint2 pack = make_uint2(*(uint32_t*)&h0, *(uint32_t*)&h1);
    *(uint2*)(g_abf + (size_t)row * KD + tid * 4) = pack;
}

// ===========================================================================
// Weight conversion: both weights in one launch, float4 -> 2x half2.
// ===========================================================================
__global__ void convert_w_kernel(const float* __restrict__ w_qkv,
                                 const float* __restrict__ w_out) {
    int idx = blockIdx.x * 256 + threadIdx.x;   // 1M total, 4 elems each
    int e4 = idx * 4;
    float4 v;
    __half* dst;
    if (e4 < EDIM*DMODEL) {
        v = *(const float4*)(w_qkv + e4);
        dst = g_bbf + e4;
    } else {
        int j = e4 - EDIM*DMODEL;
        v = *(const float4*)(w_out + j);
        dst = g_bbf2 + j;
    }
    __half2 h0 = __floats2half2_rn(v.x, v.y);
    __half2 h1 = __floats2half2_rn(v.z, v.w);
    uint2 pack = make_uint2(*(uint32_t*)&h0, *(uint32_t*)&h1);
    *(uint2*)dst = pack;
}

// ===========================================================================
// HMMA GEMM (fp16, K=1024). QKV=true: epilogue writes fp16 head-major into
// g_split. QKV=false: float C + residual.
// ===========================================================================
template<bool QKV>
__global__ __launch_bounds__(256) void gemm_mma_kernel(
    const __half* __restrict__ A, const __half* __restrict__ Bw,
    const float* __restrict__ Rsd, float* __restrict__ C, int N)
{
    __shared__ __align__(128) __half sA[2][128*40];
    __shared__ __align__(128) __half sB[2][128*40];

    int tid = threadIdx.x, lid = tid & 31, wid = tid >> 5;
    int wm = (wid & 1) * 64;
    int wn = (wid >> 1) * 32;
    int m0 = blockIdx.y * 128, n0 = blockIdx.x * 128;

    int ldrow = tid >> 1;
    int ldcol = (tid & 1) * 32;       // bytes
    const char* gA = (const char*)(A  + (size_t)(m0 + ldrow) * KD) + ldcol;
    const char* gB = (const char*)(Bw + (size_t)(n0 + ldrow) * KD) + ldcol;

    auto prefetch = [&](int c) {
        int s = c & 1;
        uint32_t da = smem_u32(&sA[s][ldrow * 40]) + (uint32_t)ldcol;
        uint32_t db = smem_u32(&sB[s][ldrow * 40]) + (uint32_t)ldcol;
        const char* a = gA + (size_t)c * 64;
        const char* b = gB + (size_t)c * 64;
        cp16(da, a);      cp16(da + 16, a + 16);
        cp16(db, b);      cp16(db + 16, b + 16);
        cp_commit();
    };

    float acc[4][4][4] = {};

    prefetch(0); prefetch(1);

    int g  = lid >> 3, r8 = lid & 7;
    int a_m = wm + (g & 1) * 8 + r8;
    int a_k = (g >> 1) * 8;
    int b_n = wn + (g >> 1) * 8 + r8;
    int b_k = (g & 1) * 8;

    for (int kt = 0; kt < NK; kt++) {
        int s = kt & 1;
        if (kt + 1 < NK) cp_wait<1>(); else cp_wait<0>();
        __syncthreads();

        uint32_t baseA = smem_u32(&sA[s][0]);
        uint32_t baseB = smem_u32(&sB[s][0]);
#pragma unroll
        for (int ks = 0; ks < 2; ks++) {
            uint32_t a[4][4], b[4][2];
#pragma unroll
            for (int mt = 0; mt < 4; mt++) {
                uint32_t addr = baseA + (uint32_t)(a_m + mt*16) * 80u
                                      + (uint32_t)(a_k + ks*16) * 2u;
                ldsm4(a[mt][0], a[mt][1], a[mt][2], a[mt][3], addr);
            }
#pragma unroll
            for (int nt = 0; nt < 2; nt++) {
                uint32_t r0, r1, r2, r3;
                uint32_t addr = baseB + (uint32_t)(b_n + nt*16) * 80u
                                      + (uint32_t)(b_k + ks*16) * 2u;
                ldsm4(r0, r1, r2, r3, addr);
                b[nt*2][0] = r0;   b[nt*2][1] = r1;
                b[nt*2+1][0] = r2; b[nt*2+1][1] = r3;
            }
#pragma unroll
            for (int mt = 0; mt < 4; mt++)
#pragma unroll
                for (int nn = 0; nn < 4; nn++)
                    mma16816(acc[mt][nn], a[mt], b[nn]);
        }
        __syncthreads();
        if (kt + 2 < NK) prefetch(kt + 2);
    }

    int row = lid >> 2, col = (lid & 3) * 2;
#pragma unroll
    for (int mt = 0; mt < 4; mt++) {
#pragma unroll
        for (int nn = 0; nn < 4; nn++) {
            int m = m0 + wm + mt*16 + row;
            int n = n0 + wn + nn*8 + col;
            if (QKV) {
                int sc = n >> 10, h = (n >> 6) & 15, d = n & 63;
                int t = m & (SEQ - 1), bb = m >> 11;
                size_t base = (size_t)sc * SEC_ELEMS
                            + ((size_t)(bb * NHEADS + h) * SEQ + t) * HDIM + d;
                __half2 v0 = __floats2half2_rn(acc[mt][nn][0], acc[mt][nn][1]);
                __half2 v1 = __floats2half2_rn(acc[mt][nn][2], acc[mt][nn][3]);
                *(__half2*)(g_split + base)            = v0;
                *(__half2*)(g_split + base + 8*HDIM)   = v1;
            } else {
                float2 v0 = make_float2(acc[mt][nn][0], acc[mt][nn][1]);
                float2 v1 = make_float2(acc[mt][nn][2], acc[mt][nn][3]);
                float2 q0 = *(const float2*)(Rsd + (size_t)m * N + n);
                float2 q1 = *(const float2*)(Rsd + (size_t)(m+8) * N + n);
                v0.x += q0.x; v0.y += q0.y;
                v1.x += q1.x; v1.y += q1.y;
                *(float2*)(C + (size_t)m * N + n)     = v0;
                *(float2*)(C + (size_t)(m+8) * N + n) = v1;
            }
        }
    }
}

// ===========================================================================
// K3: in-place fp16 RoPE on Q,K sections of g_split.
// Fast __sincosf (argument rounding matches reference's fp32 freqs).
// Q scaled by 0.125*log2(e) (exp2-domain softmax downstream).
// ===========================================================================
__global__ void rope_kernel() {
    int idx = blockIdx.x * 256 + threadIdx.x;   // BH*2*SEQ*16 = 2,097,152
    int k  = idx & 15;
    int t  = (idx >> 4) & (SEQ - 1);
    int sc = (idx >> 15) & 1;                   // 0 = q, 1 = k
    int bh = idx >> 16;
    __half* p = g_split + (size_t)sc * SEC_ELEMS + ((size_t)bh * SEQ + t) * HDIM + 2*k;
    float2 a = __half22float2(*(__half2*)(p));
    float2 b = __half22float2(*(__half2*)(p + 32));
    const float NEG_L2_10K_32 = -0.41524101186092029f;   // -log2(10000)/32
    float if0 = exp2f((float)(2*k)   * NEG_L2_10K_32);
    float if1 = exp2f((float)(2*k+1) * NEG_L2_10K_32);
    float s0, c0, s1, c1;
    __sincosf((float)t * if0, &s0, &c0);
    __sincosf((float)t * if1, &s1, &c1);
    float y0 = a.x*c0 - b.x*s0, y1 = a.y*c1 - b.y*s1;
    float z0 = b.x*c0 + a.x*s0, z1 = b.y*c1 + a.y*s1;
    if (sc == 0) {
        const float QS = 0.125f * 1.4426950408889634f;   // 1/sqrt(64) * log2(e)
        y0 *= QS; y1 *= QS; z0 *= QS; z1 *= QS;
    }
    *(__half2*)(p)      = __floats2half2_rn(y0, y1);
    *(__half2*)(p + 32) = __floats2half2_rn(z0, z1);
}

// ===========================================================================
// K4: HMMA causal flash attention, fp16 operands, exp2-domain fp32 softmax.
// grid (SEQ/64, NHEADS, BATCH), 128 threads (4 warps x 16 q-rows).
// Heavy-first: qt = gridDim.x-1-blockIdx.x. Q fragments hoisted.
// ===========================================================================
#define ATS 72                         // smem row stride in halfs
#define AT_TILE (64*ATS)               // one 64x64 array
#define ATT_SMEM ((1 + 4) * AT_TILE * 2)   // bytes = 46080

__global__ __launch_bounds__(128, 4) void attn_mma_kernel() {
    extern __shared__ __half sh[];
    __half* Qh = sh;
    __half* KV = sh + AT_TILE;   // stage s: +s*2*AT_TILE; [Kh, Vh]

    int qt = (gridDim.x - 1) - blockIdx.x;      // heavy CTAs first
    int hh = blockIdx.y, b = blockIdx.z;
    int bh = b * NHEADS + hh;
    int tid = threadIdx.x;
    int lid = tid & 31, wid = tid >> 5;
    int q0 = qt * 64;

    const __half* gq = g_split + 0*SEC_ELEMS + (size_t)bh * SEQ * HDIM;
    const __half* gk = g_split + 1*SEC_ELEMS + (size_t)bh * SEQ * HDIM;
    const __half* gv = g_split + 2*SEC_ELEMS + (size_t)bh * SEQ * HDIM;

    int ldrow = tid >> 1;          // 0..63
    int ldh   = (tid & 1) * 32;    // halfs offset within row

    // Q load (part of group 0)
    {
        const __half* s0 = gq + (size_t)(q0 + ldrow) * HDIM + ldh;
        uint32_t d0 = smem_u32(Qh + ldrow * ATS + ldh);
#pragma unroll
        for (int i = 0; i < 4; i++) cp16(d0 + i*16, s0 + i*8);
    }

    auto prefetch = [&](int kt) {
        int s = kt & 1;
        __half* base = KV + s * 2 * AT_TILE;
        size_t gr = (size_t)(kt * 64 + ldrow) * HDIM + ldh;
        const __half* srcs[2] = { gk + gr, gv + gr };
#pragma unroll
        for (int a = 0; a < 2; a++) {
            uint32_t dst = smem_u32(base + a * AT_TILE + ldrow * ATS + ldh);
#pragma unroll
            for (int i = 0; i < 4; i++) cp16(dst + i*16, srcs[a] + i*8);
        }
        cp_commit();
    };
    prefetch(0);                      // group 0 = Q + tile 0
    if (qt > 0) { prefetch(1); cp_wait<1>(); } else { cp_wait<0>(); }
    __syncthreads();

    int g  = lid >> 3, r8 = lid & 7;
    int a_row = wid * 16 + (g & 1) * 8 + r8;   // Q smem row
    int a_kof = (g >> 1) * 8;                  // + kc*16
    int b_row = (g >> 1) * 8 + r8;             // K smem row within 16-pair (+p*16)
    int b_kof = (g & 1) * 8;
    int v_row = lid & 15;                      // + kc*16
    int v_col = (lid >> 4) * 8;                // + p*16
    int qrow_loc = wid * 16 + (lid >> 2);      // local q row for c0/c1

    // ---- hoist Q fragments (loop-invariant) ----
    uint32_t aq[4][4];
    {
        uint32_t bQh = smem_u32(Qh);
#pragma unroll
        for (int kc = 0; kc < 4; kc++) {
            uint32_t aoff = (uint32_t)(a_row * ATS + kc*16 + a_kof) * 2u;
            ldsm4(aq[kc][0], aq[kc][1], aq[kc][2], aq[kc][3], bQh + aoff);
        }
    }

    float m0 = -1e30f, m1 = -1e30f, l0 = 0.f, l1 = 0.f;
    float oacc[8][4] = {};

    for (int kt = 0; kt <= qt; kt++) {
        uint32_t bKh = smem_u32(KV + (kt & 1) * 2 * AT_TILE);
        uint32_t bVh = bKh + AT_TILE * 2;

        // ---- S = Q K^T (exp2-domain: Q pre-scaled by 0.125*log2e) ----
        float sacc[8][4] = {};
#pragma unroll
        for (int kc = 0; kc < 4; kc++) {
            uint32_t bhf[8][2];
#pragma unroll
            for (int p = 0; p < 4; p++) {
                uint32_t boff = (uint32_t)((p*16 + b_row) * ATS + kc*16 + b_kof) * 2u;
                uint32_t r0, r1, r2, r3;
                ldsm4(r0, r1, r2, r3, bKh + boff);
                bhf[2*p][0] = r0; bhf[2*p][1] = r1;
                bhf[2*p+1][0] = r2; bhf[2*p+1][1] = r3;
            }
#pragma unroll
            for (int j = 0; j < 8; j++)
                mma16816(sacc[j], aq[kc], bhf[j]);
        }

        // ---- causal mask on diagonal tile ----
        if (kt == qt) {
#pragma unroll
            for (int j = 0; j < 8; j++) {
                int col = j*8 + (lid & 3) * 2;
                if (col     > qrow_loc)     sacc[j][0] = -1e30f;
                if (col + 1 > qrow_loc)     sacc[j][1] = -1e30f;
                if (col     > qrow_loc + 8) sacc[j][2] = -1e30f;
                if (col + 1 > qrow_loc + 8) sacc[j][3] = -1e30f;
            }
        }

        // ---- online softmax (exp2 domain), rows qrow_loc and +8 ----
        float mx0 = -1e30f, mx1 = -1e30f;
#pragma unroll
        for (int j = 0; j < 8; j++) {
            mx0 = fmaxf(mx0, fmaxf(sacc[j][0], sacc[j][1]));
            mx1 = fmaxf(mx1, fmaxf(sacc[j][2], sacc[j][3]));
        }
        mx0 = fmaxf(mx0, __shfl_xor_sync(0xffffffffu, mx0, 1));
        mx0 = fmaxf(mx0, __shfl_xor_sync(0xffffffffu, mx0, 2));
        mx1 = fmaxf(mx1, __shfl_xor_sync(0xffffffffu, mx1, 1));
        mx1 = fmaxf(mx1, __shfl_xor_sync(0xffffffffu, mx1, 2));
        float mn0 = fmaxf(m0, mx0), mn1 = fmaxf(m1, mx1);
        float al0 = exp2f(m0 - mn0), al1 = exp2f(m1 - mn1);
        float s0 = 0.f, s1 = 0.f;
#pragma unroll
        for (int j = 0; j < 8; j++) {
            sacc[j][0] = exp2f(sacc[j][0] - mn0);
            sacc[j][1] = exp2f(sacc[j][1] - mn0);
            sacc[j][2] = exp2f(sacc[j][2] - mn1);
            sacc[j][3] = exp2f(sacc[j][3] - mn1);
            s0 += sacc[j][0] + sacc[j][1];
            s1 += sacc[j][2] + sacc[j][3];
        }
        s0 += __shfl_xor_sync(0xffffffffu, s0, 1);
        s0 += __shfl_xor_sync(0xffffffffu, s0, 2);
        s1 += __shfl_xor_sync(0xffffffffu, s1, 1);
        s1 += __shfl_xor_sync(0xffffffffu, s1, 2);
        l0 = l0 * al0 + s0;  l1 = l1 * al1 + s1;
        m0 = mn0;  m1 = mn1;
#pragma unroll
        for (int j = 0; j < 8; j++) {
            oacc[j][0] *= al0; oacc[j][1] *= al0;
            oacc[j][2] *= al1; oacc[j][3] *= al1;
        }

        // ---- P fragments (fp16) ----
        uint32_t ph01[8], ph23[8];
#pragma unroll
        for (int j = 0; j < 8; j++) {
            __half2 t0 = __floats2half2_rn(sacc[j][0], sacc[j][1]);
            __half2 t1 = __floats2half2_rn(sacc[j][2], sacc[j][3]);
            ph01[j] = *(uint32_t*)&t0;
            ph23[j] = *(uint32_t*)&t1;
        }

        // ---- O += P V, V via ldmatrix.trans ----
#pragma unroll
        for (int kc = 0; kc < 4; kc++) {
            uint32_t aH[4] = { ph01[2*kc], ph23[2*kc], ph01[2*kc+1], ph23[2*kc+1] };
#pragma unroll
            for (int p = 0; p < 4; p++) {
                uint32_t voff = (uint32_t)((kc*16 + v_row) * ATS + p*16 + v_col) * 2u;
                uint32_t h0, h1, h2, h3;
                ldsm4t(h0, h1, h2, h3, bVh + voff);
                uint32_t bv0[2] = { h0, h1 }, bv1[2] = { h2, h3 };
                mma16816(oacc[2*p],   aH, bv0);
                mma16816(oacc[2*p+1], aH, bv1);
            }
        }

        // ---- advance pipeline ----
        if (kt < qt) {
            __syncthreads();
            if (kt + 2 <= qt) { prefetch(kt + 2); cp_wait<1>(); } else { cp_wait<0>(); }
            __syncthreads();
        }
    }

    // ---- epilogue: normalize, write fp16 into g_abf ----
    float inv0 = 1.0f / l0, inv1 = 1.0f / l1;
    int mg0 = b * SEQ + q0 + qrow_loc;
    int mg1 = mg0 + 8;
#pragma unroll
    for (int j = 0; j < 8; j++) {
        int col = hh * HDIM + j*8 + (lid & 3) * 2;
        __half2 hp0 = __floats2half2_rn(oacc[j][0] * inv0, oacc[j][1] * inv0);
        __half2 hp1 = __floats2half2_rn(oacc[j][2] * inv1, oacc[j][3] * inv1);
        *(__half2*)(g_abf + (size_t)mg0 * KD + col) = hp0;
        *(__half2*)(g_abf + (size_t)mg1 * KD + col) = hp1;
    }
}

// ===========================================================================
extern "C" void kernel_launch(void* const* d_in, const int* in_sizes, int n_in,
                              void* d_out, int out_size) {
    const float* x      = (const float*)d_in[0];
    const float* norm_w = (const float*)d_in[1];
    const float* w_qkv  = (const float*)d_in[2];
    const float* w_out  = (const float*)d_in[3];
    float* out = (float*)d_out;

    __half *p_abf, *p_bbf, *p_bbf2;
    cudaGetSymbolAddress((void**)&p_abf,  g_abf);
    cudaGetSymbolAddress((void**)&p_bbf,  g_bbf);
    cudaGetSymbolAddress((void**)&p_bbf2, g_bbf2);

    cudaFuncSetAttribute(attn_mma_kernel,
                         cudaFuncAttributeMaxDynamicSharedMemorySize, ATT_SMEM);

    // 1. RMSNorm -> fp16 (vectorized)
    rmsnorm_kernel<<<MROWS, 256>>>(x, norm_w);

    // 2. both weights -> fp16 (one launch, vectorized)
    convert_w_kernel<<<((EDIM+DMODEL)*DMODEL)/(256*4), 256>>>(w_qkv, w_out);

    // 3. QKV projection (HMMA fp16); epilogue writes head-major fp16 g_split
    gemm_mma_kernel<true><<<dim3(EDIM/128, MROWS/128), 256>>>(
        p_abf, p_bbf, nullptr, nullptr, EDIM);

    // 4. RoPE in place on Q,K (fp16, fast sincos); Q scale folds in log2(e)
    rope_kernel<<<(BH * 2 * SEQ * 16) / 256, 256>>>();

    // 5. HMMA causal flash attention (heavy-first, exp2 softmax)
    attn_mma_kernel<<<dim3(SEQ/64, NHEADS, BATCH), 128, ATT_SMEM>>>();

    // 6. Output projection + residual (HMMA fp16)
    gemm_mma_kernel<false><<<dim3(DMODEL/128, MROWS/128), 256>>>(
        p_abf, p_bbf2, x, out, DMODEL);
}

// round 11
// speedup vs baseline: 3.0625x; 1.0162x over previous
#include <cuda_runtime.h>
#include <cuda_fp16.h>
#include <math.h>
#include <stdint.h>

#define BATCH   2
#define SEQ     2048
#define DMODEL  1024
#define NHEADS  16
#define HDIM    64
#define MROWS   (BATCH*SEQ)        // 4096
#define EDIM    (3*DMODEL)         // 3072
#define KD      DMODEL             // GEMM K = 1024
#define NK      (KD/32)            // 32 k-chunks of 32
#define BH      (BATCH*NHEADS)     // 32

// Scratch (device globals; no runtime allocation allowed)
__device__ __align__(128) __half g_abf[MROWS*KD];      // fp16 activations (h, then attn-out)
__device__ __align__(128) __half g_bbf[EDIM*KD];       // fp16 w_qkv
__device__ __align__(128) __half g_bbf2[DMODEL*KD];    // fp16 w_out
// head-major fp16 q/k/v: [sec: q, k, v][bh][t][d]
__device__ __align__(128) __half g_split[(size_t)3*BH*SEQ*HDIM];
#define SEC_ELEMS ((size_t)BH*SEQ*HDIM)

// ===========================================================================
// helpers
// ===========================================================================
__device__ __forceinline__ void pdl_wait() {
    asm volatile("griddepcontrol.wait;" ::: "memory");
}
__device__ __forceinline__ uint32_t smem_u32(const void* p) {
    uint32_t a;
    asm("{ .reg .u64 t; cvta.to.shared.u64 t, %1; cvt.u32.u64 %0, t; }" : "=r"(a) : "l"(p));
    return a;
}
__device__ __forceinline__ void cp16(uint32_t smem, const void* g) {
    asm volatile("cp.async.cg.shared.global [%0], [%1], 16;" :: "r"(smem), "l"(g) : "memory");
}
__device__ __forceinline__ void cp_commit() {
    asm volatile("cp.async.commit_group;" ::: "memory");
}
template<int N> __device__ __forceinline__ void cp_wait() {
    asm volatile("cp.async.wait_group %0;" :: "n"(N) : "memory");
}
__device__ __forceinline__ void ldsm4(uint32_t& r0, uint32_t& r1, uint32_t& r2, uint32_t& r3,
                                      uint32_t addr) {
    asm volatile("ldmatrix.sync.aligned.m8n8.x4.shared.b16 {%0,%1,%2,%3}, [%4];"
                 : "=r"(r0), "=r"(r1), "=r"(r2), "=r"(r3) : "r"(addr));
}
__device__ __forceinline__ void ldsm4t(uint32_t& r0, uint32_t& r1, uint32_t& r2, uint32_t& r3,
                                       uint32_t addr) {
    asm volatile("ldmatrix.sync.aligned.m8n8.x4.trans.shared.b16 {%0,%1,%2,%3}, [%4];"
                 : "=r"(r0), "=r"(r1), "=r"(r2), "=r"(r3) : "r"(addr));
}
__device__ __forceinline__ void mma16816(float* d, const uint32_t* a, const uint32_t* b) {
    asm volatile("mma.sync.aligned.m16n8k16.row.col.f32.f16.f16.f32 "
                 "{%0,%1,%2,%3}, {%4,%5,%6,%7}, {%8,%9}, {%0,%1,%2,%3};"
                 : "+f"(d[0]), "+f"(d[1]), "+f"(d[2]), "+f"(d[3])
                 : "r"(a[0]), "r"(a[1]), "r"(a[2]), "r"(a[3]), "r"(b[0]), "r"(b[1]));
}

// ===========================================================================
// K1: merged RMSNorm + weight conversion (independent halves of the grid).
// Blocks [0, MROWS): rmsnorm row. Blocks [MROWS, MROWS+4096): weight convert.
// ===========================================================================
__global__ void prep_kernel(const float* __restrict__ x, const float* __restrict__ w,
                            const float* __restrict__ w_qkv, const float* __restrict__ w_out) {
    int tid = threadIdx.x;
    if (blockIdx.x < MROWS) {
        int row = blockIdx.x;
        float4 v = *(const float4*)(x + (size_t)row * DMODEL + tid * 4);
        float ss = v.x*v.x + v.y*v.y + v.z*v.z + v.w*v.w;
#pragma unroll
        for (int off = 16; off > 0; off >>= 1)
            ss += __shfl_xor_sync(0xffffffffu, ss, off);
        __shared__ float red[8];
        if ((tid & 31) == 0) red[tid >> 5] = ss;
        __syncthreads();
        float tot = red[0] + red[1] + red[2] + red[3]
                  + red[4] + red[5] + red[6] + red[7];
        float inv = rsqrtf(tot * (1.0f / DMODEL) + 1e-6f);
        float4 wv = *(const float4*)(w + tid * 4);
        __half2 h0 = __floats2half2_rn(v.x * inv * wv.x, v.y * inv * wv.y);
        __half2 h1 = __floats2half2_rn(v.z * inv * wv.z, v.w * inv * wv.w);
        uint2 pack = make_uint2(*(uint32_t*)&h0, *(uint32_t*)&h1);
        *(uint2*)(g_abf + (size_t)row * KD + tid * 4) = pack;
    } else {
        int idx = (blockIdx.x - MROWS) * 256 + tid;   // 1M threads, 4 elems each
        int e4 = idx * 4;
        float4 v;
        __half* dst;
        if (e4 < EDIM*DMODEL) {
            v = *(const float4*)(w_qkv + e4);
            dst = g_bbf + e4;
        } else {
            int j = e4 - EDIM*DMODEL;
            v = *(const float4*)(w_out + j);
            dst = g_bbf2 + j;
        }
        __half2 h0 = __floats2half2_rn(v.x, v.y);
        __half2 h1 = __floats2half2_rn(v.z, v.w);
        uint2 pack = make_uint2(*(uint32_t*)&h0, *(uint32_t*)&h1);
        *(uint2*)dst = pack;
    }
}

// ===========================================================================
// HMMA GEMM (fp16, K=1024). QKV=true: epilogue writes fp16 head-major into
// g_split. QKV=false: float C + residual.
// ===========================================================================
template<bool QKV>
__global__ __launch_bounds__(256) void gemm_mma_kernel(
    const __half* __restrict__ A, const __half* __restrict__ Bw,
    const float* __restrict__ Rsd, float* __restrict__ C, int N)
{
    __shared__ __align__(128) __half sA[2][128*40];
    __shared__ __align__(128) __half sB[2][128*40];

    pdl_wait();   // PDL: block until predecessor grid's stores are visible

    int tid = threadIdx.x, lid = tid & 31, wid = tid >> 5;
    int wm = (wid & 1) * 64;
    int wn = (wid >> 1) * 32;
    int m0 = blockIdx.y * 128, n0 = blockIdx.x * 128;

    int ldrow = tid >> 1;
    int ldcol = (tid & 1) * 32;       // bytes
    const char* gA = (const char*)(A  + (size_t)(m0 + ldrow) * KD) + ldcol;
    const char* gB = (const char*)(Bw + (size_t)(n0 + ldrow) * KD) + ldcol;

    auto prefetch = [&](int c) {
        int s = c & 1;
        uint32_t da = smem_u32(&sA[s][ldrow * 40]) + (uint32_t)ldcol;
        uint32_t db = smem_u32(&sB[s][ldrow * 40]) + (uint32_t)ldcol;
        const char* a = gA + (size_t)c * 64;
        const char* b = gB + (size_t)c * 64;
        cp16(da, a);      cp16(da + 16, a + 16);
        cp16(db, b);      cp16(db + 16, b + 16);
        cp_commit();
    };

    float acc[4][4][4] = {};

    prefetch(0); prefetch(1);

    int g  = lid >> 3, r8 = lid & 7;
    int a_m = wm + (g & 1) * 8 + r8;
    int a_k = (g >> 1) * 8;
    int b_n = wn + (g >> 1) * 8 + r8;
    int b_k = (g & 1) * 8;

    for (int kt = 0; kt < NK; kt++) {
        int s = kt & 1;
        if (kt + 1 < NK) cp_wait<1>(); else cp_wait<0>();
        __syncthreads();

        uint32_t baseA = smem_u32(&sA[s][0]);
        uint32_t baseB = smem_u32(&sB[s][0]);
#pragma unroll
        for (int ks = 0; ks < 2; ks++) {
            uint32_t a[4][4], b[4][2];
#pragma unroll
            for (int mt = 0; mt < 4; mt++) {
                uint32_t addr = baseA + (uint32_t)(a_m + mt*16) * 80u
                                      + (uint32_t)(a_k + ks*16) * 2u;
                ldsm4(a[mt][0], a[mt][1], a[mt][2], a[mt][3], addr);
            }
#pragma unroll
            for (int nt = 0; nt < 2; nt++) {
                uint32_t r0, r1, r2, r3;
                uint32_t addr = baseB + (uint32_t)(b_n + nt*16) * 80u
                                      + (uint32_t)(b_k + ks*16) * 2u;
                ldsm4(r0, r1, r2, r3, addr);
                b[nt*2][0] = r0;   b[nt*2][1] = r1;
                b[nt*2+1][0] = r2; b[nt*2+1][1] = r3;
            }
#pragma unroll
            for (int mt = 0; mt < 4; mt++)
#pragma unroll
                for (int nn = 0; nn < 4; nn++)
                    mma16816(acc[mt][nn], a[mt], b[nn]);
        }
        __syncthreads();
        if (kt + 2 < NK) prefetch(kt + 2);
    }

    int row = lid >> 2, col = (lid & 3) * 2;
#pragma unroll
    for (int mt = 0; mt < 4; mt++) {
#pragma unroll
        for (int nn = 0; nn < 4; nn++) {
            int m = m0 + wm + mt*16 + row;
            int n = n0 + wn + nn*8 + col;
            if (QKV) {
                int sc = n >> 10, h = (n >> 6) & 15, d = n & 63;
                int t = m & (SEQ - 1), bb = m >> 11;
                size_t base = (size_t)sc * SEC_ELEMS
                            + ((size_t)(bb * NHEADS + h) * SEQ + t) * HDIM + d;
                __half2 v0 = __floats2half2_rn(acc[mt][nn][0], acc[mt][nn][1]);
                __half2 v1 = __floats2half2_rn(acc[mt][nn][2], acc[mt][nn][3]);
                *(__half2*)(g_split + base)            = v0;
                *(__half2*)(g_split + base + 8*HDIM)   = v1;
            } else {
                float2 v0 = make_float2(acc[mt][nn][0], acc[mt][nn][1]);
                float2 v1 = make_float2(acc[mt][nn][2], acc[mt][nn][3]);
                float2 q0 = *(const float2*)(Rsd + (size_t)m * N + n);
                float2 q1 = *(const float2*)(Rsd + (size_t)(m+8) * N + n);
                v0.x += q0.x; v0.y += q0.y;
                v1.x += q1.x; v1.y += q1.y;
                *(float2*)(C + (size_t)m * N + n)     = v0;
                *(float2*)(C + (size_t)(m+8) * N + n) = v1;
            }
        }
    }
}

// ===========================================================================
// K3: in-place fp16 RoPE on Q,K sections of g_split.
// Fast __sincosf; Q scaled by 0.125*log2(e) (exp2-domain softmax downstream).
// ===========================================================================
__global__ void rope_kernel() {
    pdl_wait();
    int idx = blockIdx.x * 256 + threadIdx.x;   // BH*2*SEQ*16 = 2,097,152
    int k  = idx & 15;
    int t  = (idx >> 4) & (SEQ - 1);
    int sc = (idx >> 15) & 1;                   // 0 = q, 1 = k
    int bh = idx >> 16;
    __half* p = g_split + (size_t)sc * SEC_ELEMS + ((size_t)bh * SEQ + t) * HDIM + 2*k;
    float2 a = __half22float2(*(__half2*)(p));
    float2 b = __half22float2(*(__half2*)(p + 32));
    const float NEG_L2_10K_32 = -0.41524101186092029f;   // -log2(10000)/32
    float if0 = exp2f((float)(2*k)   * NEG_L2_10K_32);
    float if1 = exp2f((float)(2*k+1) * NEG_L2_10K_32);
    float s0, c0, s1, c1;
    __sincosf((float)t * if0, &s0, &c0);
    __sincosf((float)t * if1, &s1, &c1);
    float y0 = a.x*c0 - b.x*s0, y1 = a.y*c1 - b.y*s1;
    float z0 = b.x*c0 + a.x*s0, z1 = b.y*c1 + a.y*s1;
    if (sc == 0) {
        const float QS = 0.125f * 1.4426950408889634f;   // 1/sqrt(64) * log2(e)
        y0 *= QS; y1 *= QS; z0 *= QS; z1 *= QS;
    }
    *(__half2*)(p)      = __floats2half2_rn(y0, y1);
    *(__half2*)(p + 32) = __floats2half2_rn(z0, z1);
}

// ===========================================================================
// K4: HMMA causal flash attention, fp16 operands, exp2-domain fp32 softmax.
// grid (SEQ/64, NHEADS, BATCH), 128 threads (4 warps x 16 q-rows).
// Heavy-first: qt = gridDim.x-1-blockIdx.x. Q fragments hoisted.
// ===========================================================================
#define ATS 72                         // smem row stride in halfs
#define AT_TILE (64*ATS)               // one 64x64 array
#define ATT_SMEM ((1 + 4) * AT_TILE * 2)   // bytes = 46080

__global__ __launch_bounds__(128, 4) void attn_mma_kernel() {
    extern __shared__ __half sh[];
    __half* Qh = sh;
    __half* KV = sh + AT_TILE;   // stage s: +s*2*AT_TILE; [Kh, Vh]

    pdl_wait();

    int qt = (gridDim.x - 1) - blockIdx.x;      // heavy CTAs first
    int hh = blockIdx.y, b = blockIdx.z;
    int bh = b * NHEADS + hh;
    int tid = threadIdx.x;
    int lid = tid & 31, wid = tid >> 5;
    int q0 = qt * 64;

    const __half* gq = g_split + 0*SEC_ELEMS + (size_t)bh * SEQ * HDIM;
    const __half* gk = g_split + 1*SEC_ELEMS + (size_t)bh * SEQ * HDIM;
    const __half* gv = g_split + 2*SEC_ELEMS + (size_t)bh * SEQ * HDIM;

    int ldrow = tid >> 1;          // 0..63
    int ldh   = (tid & 1) * 32;    // halfs offset within row

    // Q load (part of group 0)
    {
        const __half* s0 = gq + (size_t)(q0 + ldrow) * HDIM + ldh;
        uint32_t d0 = smem_u32(Qh + ldrow * ATS + ldh);
#pragma unroll
        for (int i = 0; i < 4; i++) cp16(d0 + i*16, s0 + i*8);
    }

    auto prefetch = [&](int kt) {
        int s = kt & 1;
        __half* base = KV + s * 2 * AT_TILE;
        size_t gr = (size_t)(kt * 64 + ldrow) * HDIM + ldh;
        const __half* srcs[2] = { gk + gr, gv + gr };
#pragma unroll
        for (int a = 0; a < 2; a++) {
            uint32_t dst = smem_u32(base + a * AT_TILE + ldrow * ATS + ldh);
#pragma unroll
            for (int i = 0; i < 4; i++) cp16(dst + i*16, srcs[a] + i*8);
        }
        cp_commit();
    };
    prefetch(0);                      // group 0 = Q + tile 0
    if (qt > 0) { prefetch(1); cp_wait<1>(); } else { cp_wait<0>(); }
    __syncthreads();

    int g  = lid >> 3, r8 = lid & 7;
    int a_row = wid * 16 + (g & 1) * 8 + r8;   // Q smem row
    int a_kof = (g >> 1) * 8;                  // + kc*16
    int b_row = (g >> 1) * 8 + r8;             // K smem row within 16-pair (+p*16)
    int b_kof = (g & 1) * 8;
    int v_row = lid & 15;                      // + kc*16
    int v_col = (lid >> 4) * 8;                // + p*16
    int qrow_loc = wid * 16 + (lid >> 2);      // local q row for c0/c1

    // ---- hoist Q fragments (loop-invariant) ----
    uint32_t aq[4][4];
    {
        uint32_t bQh = smem_u32(Qh);
#pragma unroll
        for (int kc = 0; kc < 4; kc++) {
            uint32_t aoff = (uint32_t)(a_row * ATS + kc*16 + a_kof) * 2u;
            ldsm4(aq[kc][0], aq[kc][1], aq[kc][2], aq[kc][3], bQh + aoff);
        }
    }

    float m0 = -1e30f, m1 = -1e30f, l0 = 0.f, l1 = 0.f;
    float oacc[8][4] = {};

    for (int kt = 0; kt <= qt; kt++) {
        uint32_t bKh = smem_u32(KV + (kt & 1) * 2 * AT_TILE);
        uint32_t bVh = bKh + AT_TILE * 2;

        // ---- S = Q K^T (exp2-domain: Q pre-scaled by 0.125*log2e) ----
        float sacc[8][4] = {};
#pragma unroll
        for (int kc = 0; kc < 4; kc++) {
            uint32_t bhf[8][2];
#pragma unroll
            for (int p = 0; p < 4; p++) {
                uint32_t boff = (uint32_t)((p*16 + b_row) * ATS + kc*16 + b_kof) * 2u;
                uint32_t r0, r1, r2, r3;
                ldsm4(r0, r1, r2, r3, bKh + boff);
                bhf[2*p][0] = r0; bhf[2*p][1] = r1;
                bhf[2*p+1][0] = r2; bhf[2*p+1][1] = r3;
            }
#pragma unroll
            for (int j = 0; j < 8; j++)
                mma16816(sacc[j], aq[kc], bhf[j]);
        }

        // ---- causal mask on diagonal tile ----
        if (kt == qt) {
#pragma unroll
            for (int j = 0; j < 8; j++) {
                int col = j*8 + (lid & 3) * 2;
                if (col     > qrow_loc)     sacc[j][0] = -1e30f;
                if (col + 1 > qrow_loc)     sacc[j][1] = -1e30f;
                if (col     > qrow_loc + 8) sacc[j][2] = -1e30f;
                if (col + 1 > qrow_loc + 8) sacc[j][3] = -1e30f;
            }
        }

        // ---- online softmax (exp2 domain), rows qrow_loc and +8 ----
        float mx0 = -1e30f, mx1 = -1e30f;
#pragma unroll
        for (int j = 0; j < 8; j++) {
            mx0 = fmaxf(mx0, fmaxf(sacc[j][0], sacc[j][1]));
            mx1 = fmaxf(mx1, fmaxf(sacc[j][2], sacc[j][3]));
        }
        mx0 = fmaxf(mx0, __shfl_xor_sync(0xffffffffu, mx0, 1));
        mx0 = fmaxf(mx0, __shfl_xor_sync(0xffffffffu, mx0, 2));
        mx1 = fmaxf(mx1, __shfl_xor_sync(0xffffffffu, mx1, 1));
        mx1 = fmaxf(mx1, __shfl_xor_sync(0xffffffffu, mx1, 2));
        float mn0 = fmaxf(m0, mx0), mn1 = fmaxf(m1, mx1);
        float al0 = exp2f(m0 - mn0), al1 = exp2f(m1 - mn1);
        float s0 = 0.f, s1 = 0.f;
#pragma unroll
        for (int j = 0; j < 8; j++) {
            sacc[j][0] = exp2f(sacc[j][0] - mn0);
            sacc[j][1] = exp2f(sacc[j][1] - mn0);
            sacc[j][2] = exp2f(sacc[j][2] - mn1);
            sacc[j][3] = exp2f(sacc[j][3] - mn1);
            s0 += sacc[j][0] + sacc[j][1];
            s1 += sacc[j][2] + sacc[j][3];
        }
        s0 += __shfl_xor_sync(0xffffffffu, s0, 1);
        s0 += __shfl_xor_sync(0xffffffffu, s0, 2);
        s1 += __shfl_xor_sync(0xffffffffu, s1, 1);
        s1 += __shfl_xor_sync(0xffffffffu, s1, 2);
        l0 = l0 * al0 + s0;  l1 = l1 * al1 + s1;
        m0 = mn0;  m1 = mn1;
#pragma unroll
        for (int j = 0; j < 8; j++) {
            oacc[j][0] *= al0; oacc[j][1] *= al0;
            oacc[j][2] *= al1; oacc[j][3] *= al1;
        }

        // ---- P fragments (fp16) ----
        uint32_t ph01[8], ph23[8];
#pragma unroll
        for (int j = 0; j < 8; j++) {
            __half2 t0 = __floats2half2_rn(sacc[j][0], sacc[j][1]);
            __half2 t1 = __floats2half2_rn(sacc[j][2], sacc[j][3]);
            ph01[j] = *(uint32_t*)&t0;
            ph23[j] = *(uint32_t*)&t1;
        }

        // ---- O += P V, V via ldmatrix.trans ----
#pragma unroll
        for (int kc = 0; kc < 4; kc++) {
            uint32_t aH[4] = { ph01[2*kc], ph23[2*kc], ph01[2*kc+1], ph23[2*kc+1] };
#pragma unroll
            for (int p = 0; p < 4; p++) {
                uint32_t voff = (uint32_t)((kc*16 + v_row) * ATS + p*16 + v_col) * 2u;
                uint32_t h0, h1, h2, h3;
                ldsm4t(h0, h1, h2, h3, bVh + voff);
                uint32_t bv0[2] = { h0, h1 }, bv1[2] = { h2, h3 };
                mma16816(oacc[2*p],   aH, bv0);
                mma16816(oacc[2*p+1], aH, bv1);
            }
        }

        // ---- advance pipeline ----
        if (kt < qt) {
            __syncthreads();
            if (kt + 2 <= qt) { prefetch(kt + 2); cp_wait<1>(); } else { cp_wait<0>(); }
            __syncthreads();
        }
    }

    // ---- epilogue: normalize, write fp16 into g_abf ----
    float inv0 = 1.0f / l0, inv1 = 1.0f / l1;
    int mg0 = b * SEQ + q0 + qrow_loc;
    int mg1 = mg0 + 8;
#pragma unroll
    for (int j = 0; j < 8; j++) {
        int col = hh * HDIM + j*8 + (lid & 3) * 2;
        __half2 hp0 = __floats2half2_rn(oacc[j][0] * inv0, oacc[j][1] * inv0);
        __half2 hp1 = __floats2half2_rn(oacc[j][2] * inv1, oacc[j][3] * inv1);
        *(__half2*)(g_abf + (size_t)mg0 * KD + col) = hp0;
        *(__half2*)(g_abf + (size_t)mg1 * KD + col) = hp1;
    }
}

// ===========================================================================
extern "C" void kernel_launch(void* const* d_in, const int* in_sizes, int n_in,
                              void* d_out, int out_size) {
    const float* x      = (const float*)d_in[0];
    const float* norm_w = (const float*)d_in[1];
    const float* w_qkv  = (const float*)d_in[2];
    const float* w_out  = (const float*)d_in[3];
    float* out = (float*)d_out;

    __half *p_abf, *p_bbf, *p_bbf2;
    cudaGetSymbolAddress((void**)&p_abf,  g_abf);
    cudaGetSymbolAddress((void**)&p_bbf,  g_bbf);
    cudaGetSymbolAddress((void**)&p_bbf2, g_bbf2);

    cudaFuncSetAttribute(attn_mma_kernel,
                         cudaFuncAttributeMaxDynamicSharedMemorySize, ATT_SMEM);

    // PDL attribute shared by all dependent launches
    cudaLaunchAttribute pdl[1];
    pdl[0].id = cudaLaunchAttributeProgrammaticStreamSerialization;
    pdl[0].val.programmaticStreamSerializationAllowed = 1;

    // 1. merged RMSNorm + weight convert (no predecessor)
    prep_kernel<<<MROWS + ((EDIM+DMODEL)*DMODEL)/(256*4), 256>>>(x, norm_w, w_qkv, w_out);

    // 2. QKV projection (HMMA fp16); epilogue writes head-major fp16 g_split
    {
        cudaLaunchConfig_t cfg = {};
        cfg.gridDim = dim3(EDIM/128, MROWS/128);
        cfg.blockDim = dim3(256);
        cfg.attrs = pdl; cfg.numAttrs = 1;
        cudaLaunchKernelEx(&cfg, gemm_mma_kernel<true>,
                           (const __half*)p_abf, (const __half*)p_bbf,
                           (const float*)nullptr, (float*)nullptr, (int)EDIM);
    }

    // 3. RoPE in place on Q,K
    {
        cudaLaunchConfig_t cfg = {};
        cfg.gridDim = dim3((BH * 2 * SEQ * 16) / 256);
        cfg.blockDim = dim3(256);
        cfg.attrs = pdl; cfg.numAttrs = 1;
        cudaLaunchKernelEx(&cfg, rope_kernel);
    }

    // 4. HMMA causal flash attention (heavy-first, exp2 softmax)
    {
        cudaLaunchConfig_t cfg = {};
        cfg.gridDim = dim3(SEQ/64, NHEADS, BATCH);
        cfg.blockDim = dim3(128);
        cfg.dynamicSmemBytes = ATT_SMEM;
        cfg.attrs = pdl; cfg.numAttrs = 1;
        cudaLaunchKernelEx(&cfg, attn_mma_kernel);
    }

    // 5. Output projection + residual (HMMA fp16)
    {
        cudaLaunchConfig_t cfg = {};
        cfg.gridDim = dim3(DMODEL/128, MROWS/128);
        cfg.blockDim = dim3(256);
        cfg.attrs = pdl; cfg.numAttrs = 1;
        cudaLaunchKernelEx(&cfg, gemm_mma_kernel<false>,
                           (const __half*)p_abf, (const __half*)p_bbf2,
                           (const float*)x, (float*)out, (int)DMODEL);
    }
}